// round 1
// baseline (speedup 1.0000x reference)
#include <cuda_runtime.h>
#include <math.h>

#define BS   1024
#define SEQ  360
#define DIM  512
#define MTOT (BS*SEQ)
#define TM   128
#define TN   128
#define KS   16

// Scratch (no device allocation allowed)
__device__ float g_hproj[BS * DIM];   // relu(hidden @ W2^T + b2)
__device__ float g_score[BS * SEQ];   // pre-softmax scores

// ---------------------------------------------------------------------------
// Kernel A: h_proj[b,u] = relu( sum_k hidden[b,k]*W2[u,k] + b2[u] )
// Classic 128x128 tile SGEMM, M=1024 N=512 K=512. grid (8,4), 256 threads.
// ---------------------------------------------------------------------------
__global__ void __launch_bounds__(256) hproj_kernel(
    const float* __restrict__ A,    // hidden [1024,512]
    const float* __restrict__ B,    // W2_w   [512,512] (row-major, K contiguous)
    const float* __restrict__ bias) // W2_b   [512]
{
    __shared__ float As[KS][TM + 4];
    __shared__ float Bs[KS][TN + 4];

    const int tid = threadIdx.x;
    const int tx  = tid & 15;
    const int ty  = tid >> 4;
    const int m0  = blockIdx.x * TM;
    const int n0  = blockIdx.y * TN;

    float acc[8][8];
    #pragma unroll
    for (int i = 0; i < 8; ++i)
        #pragma unroll
        for (int j = 0; j < 8; ++j) acc[i][j] = 0.f;

    for (int kk = 0; kk < DIM; kk += KS) {
        __syncthreads();
        #pragma unroll
        for (int t = 0; t < 2; ++t) {
            int f   = tid + t * 256;
            int row = f >> 2, seg = f & 3;
            float4 v = *reinterpret_cast<const float4*>(A + (size_t)(m0 + row) * DIM + kk + seg * 4);
            As[seg*4+0][row] = v.x; As[seg*4+1][row] = v.y;
            As[seg*4+2][row] = v.z; As[seg*4+3][row] = v.w;
            float4 w = *reinterpret_cast<const float4*>(B + (size_t)(n0 + row) * DIM + kk + seg * 4);
            Bs[seg*4+0][row] = w.x; Bs[seg*4+1][row] = w.y;
            Bs[seg*4+2][row] = w.z; Bs[seg*4+3][row] = w.w;
        }
        __syncthreads();
        #pragma unroll
        for (int k = 0; k < KS; ++k) {
            float a[8], b[8];
            const float4* ap = reinterpret_cast<const float4*>(&As[k][ty * 8]);
            const float4* bp = reinterpret_cast<const float4*>(&Bs[k][tx * 8]);
            float4 a0 = ap[0], a1 = ap[1];
            float4 b0 = bp[0], b1 = bp[1];
            a[0]=a0.x; a[1]=a0.y; a[2]=a0.z; a[3]=a0.w;
            a[4]=a1.x; a[5]=a1.y; a[6]=a1.z; a[7]=a1.w;
            b[0]=b0.x; b[1]=b0.y; b[2]=b0.z; b[3]=b0.w;
            b[4]=b1.x; b[5]=b1.y; b[6]=b1.z; b[7]=b1.w;
            #pragma unroll
            for (int i = 0; i < 8; ++i)
                #pragma unroll
                for (int j = 0; j < 8; ++j)
                    acc[i][j] += a[i] * b[j];
        }
    }

    #pragma unroll
    for (int i = 0; i < 8; ++i) {
        int m = m0 + ty * 8 + i;
        #pragma unroll
        for (int j = 0; j < 8; ++j) {
            int n = n0 + tx * 8 + j;
            float v = acc[i][j] + bias[n];
            g_hproj[(size_t)m * DIM + n] = v > 0.f ? v : 0.f;
        }
    }
}

// ---------------------------------------------------------------------------
// Kernel B: fused score GEMM.
// score[m] = V_b + sum_u V[u]*tanh( relu(features[m]@W1[u] + b1[u]) + hproj[b,u] )
// Block tile: 128 rows x full 512 units (4 N-tiles looped in-block -> no atomics).
// Deterministic cross-thread reduction via shared memory, fixed order.
// ---------------------------------------------------------------------------
__global__ void __launch_bounds__(256) score_kernel(
    const float* __restrict__ A,   // features [368640, 512]
    const float* __restrict__ W1,  // [512,512]
    const float* __restrict__ b1,  // [512]
    const float* __restrict__ Vw,  // [512]
    const float* __restrict__ Vb)  // [1]
{
    __shared__ float As[KS][TM + 4];
    __shared__ float Bs[KS][TN + 4];
    __shared__ float part[TM][17];   // padded: conflict-free column sum
    __shared__ float score_s[TM];

    const int tid = threadIdx.x;
    const int tx  = tid & 15;
    const int ty  = tid >> 4;
    const int m0  = blockIdx.x * TM;

    if (tid < TM) score_s[tid] = 0.f;

    for (int nb = 0; nb < 4; ++nb) {
        const int n0 = nb * TN;

        float acc[8][8];
        #pragma unroll
        for (int i = 0; i < 8; ++i)
            #pragma unroll
            for (int j = 0; j < 8; ++j) acc[i][j] = 0.f;

        for (int kk = 0; kk < DIM; kk += KS) {
            __syncthreads();
            #pragma unroll
            for (int t = 0; t < 2; ++t) {
                int f   = tid + t * 256;
                int row = f >> 2, seg = f & 3;
                float4 v = *reinterpret_cast<const float4*>(A + (size_t)(m0 + row) * DIM + kk + seg * 4);
                As[seg*4+0][row] = v.x; As[seg*4+1][row] = v.y;
                As[seg*4+2][row] = v.z; As[seg*4+3][row] = v.w;
                float4 w = *reinterpret_cast<const float4*>(W1 + (size_t)(n0 + row) * DIM + kk + seg * 4);
                Bs[seg*4+0][row] = w.x; Bs[seg*4+1][row] = w.y;
                Bs[seg*4+2][row] = w.z; Bs[seg*4+3][row] = w.w;
            }
            __syncthreads();
            #pragma unroll
            for (int k = 0; k < KS; ++k) {
                float a[8], b[8];
                const float4* ap = reinterpret_cast<const float4*>(&As[k][ty * 8]);
                const float4* bp = reinterpret_cast<const float4*>(&Bs[k][tx * 8]);
                float4 a0 = ap[0], a1 = ap[1];
                float4 b0 = bp[0], b1v = bp[1];
                a[0]=a0.x; a[1]=a0.y; a[2]=a0.z; a[3]=a0.w;
                a[4]=a1.x; a[5]=a1.y; a[6]=a1.z; a[7]=a1.w;
                b[0]=b0.x; b[1]=b0.y; b[2]=b0.z; b[3]=b0.w;
                b[4]=b1v.x; b[5]=b1v.y; b[6]=b1v.z; b[7]=b1v.w;
                #pragma unroll
                for (int i = 0; i < 8; ++i)
                    #pragma unroll
                    for (int j = 0; j < 8; ++j)
                        acc[i][j] += a[i] * b[j];
            }
        }

        // Epilogue for this N-tile: bias, relu, +hproj, tanh, dot with V.
        float bb[8], vv[8];
        #pragma unroll
        for (int j = 0; j < 8; ++j) {
            int n = n0 + tx * 8 + j;
            bb[j] = b1[n];
            vv[j] = Vw[n];
        }

        float rowpart[8];
        #pragma unroll
        for (int i = 0; i < 8; ++i) {
            int m = m0 + ty * 8 + i;
            int bidx = m / SEQ;
            const float* hp = g_hproj + (size_t)bidx * DIM + n0 + tx * 8;
            float p = 0.f;
            #pragma unroll
            for (int j = 0; j < 8; ++j) {
                float t = acc[i][j] + bb[j];
                t = t > 0.f ? t : 0.f;
                t += hp[j];
                p += vv[j] * tanhf(t);
            }
            rowpart[i] = p;
        }

        __syncthreads();  // protect part[] reuse across nb iterations
        #pragma unroll
        for (int i = 0; i < 8; ++i) part[ty * 8 + i][tx] = rowpart[i];
        __syncthreads();

        if (tid < TM) {
            float s = 0.f;
            #pragma unroll
            for (int x = 0; x < 16; ++x) s += part[tid][x];  // fixed order: deterministic
            score_s[tid] += s;
        }
    }

    __syncthreads();
    if (tid < TM) {
        int m = m0 + tid;          // m = b*SEQ + s  -> direct index into g_score
        g_score[m] = score_s[tid] + Vb[0];
    }
}

// ---------------------------------------------------------------------------
// Kernel C: per-batch softmax over SEQ + weighted context sum.
// out layout: [0, BS*DIM) = context_vector; [BS*DIM, BS*DIM+BS*SEQ) = weights.
// ---------------------------------------------------------------------------
__global__ void __launch_bounds__(512) softmax_ctx_kernel(
    const float* __restrict__ features,  // [BS, SEQ, DIM]
    float* __restrict__ out)
{
    __shared__ float w[SEQ];
    __shared__ float red[512];

    const int b   = blockIdx.x;
    const int tid = threadIdx.x;  // 512 threads

    float sc = (tid < SEQ) ? g_score[b * SEQ + tid] : -3.4e38f;
    red[tid] = sc;
    __syncthreads();
    #pragma unroll
    for (int off = 256; off > 0; off >>= 1) {
        if (tid < off) red[tid] = fmaxf(red[tid], red[tid + off]);
        __syncthreads();
    }
    float mx = red[0];
    __syncthreads();

    float e = (tid < SEQ) ? expf(sc - mx) : 0.f;
    red[tid] = e;
    __syncthreads();
    #pragma unroll
    for (int off = 256; off > 0; off >>= 1) {
        if (tid < off) red[tid] += red[tid + off];
        __syncthreads();
    }
    float inv = 1.f / red[0];

    float wt = e * inv;
    if (tid < SEQ) {
        w[tid] = wt;
        out[(size_t)BS * DIM + (size_t)b * SEQ + tid] = wt;
    }
    __syncthreads();

    // context[b, e] = sum_s w[s] * features[b, s, e]; one thread per e (coalesced)
    float acc = 0.f;
    const float* fb = features + (size_t)b * SEQ * DIM + tid;
    #pragma unroll 4
    for (int s = 0; s < SEQ; ++s)
        acc += w[s] * fb[(size_t)s * DIM];
    out[(size_t)b * DIM + tid] = acc;
}

// ---------------------------------------------------------------------------
extern "C" void kernel_launch(void* const* d_in, const int* in_sizes, int n_in,
                              void* d_out, int out_size)
{
    const float* hidden   = (const float*)d_in[0];  // [1,1024,512]
    const float* features = (const float*)d_in[1];  // [1024,360,512]
    const float* W1_w     = (const float*)d_in[2];  // [512,512]
    const float* W1_b     = (const float*)d_in[3];  // [512]
    const float* W2_w     = (const float*)d_in[4];  // [512,512]
    const float* W2_b     = (const float*)d_in[5];  // [512]
    const float* V_w      = (const float*)d_in[6];  // [1,512]
    const float* V_b      = (const float*)d_in[7];  // [1]
    float* out = (float*)d_out;

    hproj_kernel<<<dim3(BS / TM, DIM / TN), 256>>>(hidden, W2_w, W2_b);
    score_kernel<<<MTOT / TM, 256>>>(features, W1_w, W1_b, V_w, V_b);
    softmax_ctx_kernel<<<BS, 512>>>(features, out);
}

// round 3
// speedup vs baseline: 1.8925x; 1.8925x over previous
#include <cuda_runtime.h>
#include <cuda_bf16.h>
#include <math.h>
#include <stdint.h>

#define BS   1024
#define SEQ  360
#define DIM  512
#define MTOT (BS*SEQ)

// ===================== scratch =====================
__device__ float g_hproj[BS * DIM];   // relu(hidden @ W2^T + b2)
__device__ float g_score[BS * SEQ];   // pre-softmax scores

// ===================== helpers =====================
__device__ __forceinline__ uint32_t smem_u32(const void* p) {
    uint32_t a;
    asm("{ .reg .u64 t; cvta.to.shared.u64 t, %1; cvt.u32.u64 %0, t; }" : "=r"(a) : "l"(p));
    return a;
}

__device__ __forceinline__ void ldsm4(uint32_t* r, uint32_t addr) {
    asm volatile("ldmatrix.sync.aligned.m8n8.x4.shared.b16 {%0,%1,%2,%3}, [%4];"
                 : "=r"(r[0]), "=r"(r[1]), "=r"(r[2]), "=r"(r[3]) : "r"(addr));
}

__device__ __forceinline__ void mma16816(float* c, const uint32_t* a, uint32_t b0, uint32_t b1) {
    asm volatile("mma.sync.aligned.m16n8k16.row.col.f32.bf16.bf16.f32 "
                 "{%0,%1,%2,%3}, {%4,%5,%6,%7}, {%8,%9}, {%0,%1,%2,%3};"
                 : "+f"(c[0]), "+f"(c[1]), "+f"(c[2]), "+f"(c[3])
                 : "r"(a[0]), "r"(a[1]), "r"(a[2]), "r"(a[3]), "r"(b0), "r"(b1));
}

__device__ __forceinline__ uint32_t pk2(__nv_bfloat16 a, __nv_bfloat16 b) {
    return (uint32_t)__bfloat16_as_ushort(a) | ((uint32_t)__bfloat16_as_ushort(b) << 16);
}

// split fp32x4 -> bf16 hi (round) + bf16 lo (residual), store 8B each
__device__ __forceinline__ void split_store4(float4 x, __nv_bfloat16* ph, __nv_bfloat16* pl) {
    __nv_bfloat16 h0 = __float2bfloat16(x.x), h1 = __float2bfloat16(x.y);
    __nv_bfloat16 h2 = __float2bfloat16(x.z), h3 = __float2bfloat16(x.w);
    float r0 = x.x - __bfloat162float(h0), r1 = x.y - __bfloat162float(h1);
    float r2 = x.z - __bfloat162float(h2), r3 = x.w - __bfloat162float(h3);
    uint2 uh, ul;
    uh.x = pk2(h0, h1); uh.y = pk2(h2, h3);
    ul.x = pk2(__float2bfloat16(r0), __float2bfloat16(r1));
    ul.y = pk2(__float2bfloat16(r2), __float2bfloat16(r3));
    *(uint2*)ph = uh;
    *(uint2*)pl = ul;
}

__device__ __forceinline__ float tanh_pos(float x) {
    // x >= 0 guaranteed. tanh = 1 - 2/(e^{2x}+1)
    float e = __expf(2.0f * x);
    return 1.0f - __fdividef(2.0f, e + 1.0f);
}

// ===================== score GEMM via mma.sync bf16 (split fp32) =====================
// CTA: 64 rows x 512 units; A (features slab) full-K resident in smem as hi/lo bf16.
// nb loop over 8 N-tiles of 64 units; W1 streamed per 64-k chunk, double buffered.
#define MTILE  64
#define APITCH 520                 // bf16 elems; 1040B, mod 128 = 16 -> ldmatrix conflict-free
#define BPITCH 72                  // 144B, mod 128 = 16
#define BSZ    (64*BPITCH*2)       // one B split buffer: 9216 B

#define OFF_AH  0
#define OFF_AL  (MTILE*APITCH*2)             // 66560
#define OFF_B   (2*MTILE*APITCH*2)           // 133120; layout [buf][split] x BSZ
#define OFF_B1  (OFF_B + 4*BSZ)              // 169984
#define OFF_VW  (OFF_B1 + 2048)              // 172032
#define OFF_HP  (OFF_VW + 2048)              // 174080  (2 x 512 floats)
#define OFF_RED (OFF_HP + 4096)              // 178176  (128 floats)
#define SMEM_BYTES (OFF_RED + 512)           // 178688

__global__ void __launch_bounds__(256, 1)
score_mma_kernel(const float* __restrict__ A,   // features [368640, 512]
                 const float* __restrict__ W1,  // [512, 512]
                 const float* __restrict__ b1,  // [512]
                 const float* __restrict__ Vw,  // [512]
                 const float* __restrict__ Vb)  // [1]
{
    extern __shared__ char sm[];
    const uint32_t smbase = smem_u32(sm);

    const int tid  = threadIdx.x;
    const int lane = tid & 31;
    const int wid  = tid >> 5;
    const int wm   = wid & 3;       // 4 m-subtiles of 16
    const int wn   = wid >> 2;      // 2 n-subtiles of 32
    const int m0   = blockIdx.x * MTILE;
    const int bidx0 = m0 / SEQ;

    __nv_bfloat16* a_hi = (__nv_bfloat16*)(sm + OFF_AH);
    __nv_bfloat16* a_lo = (__nv_bfloat16*)(sm + OFF_AL);
    float* s_b1  = (float*)(sm + OFF_B1);
    float* s_vw  = (float*)(sm + OFF_VW);
    float* s_hp  = (float*)(sm + OFF_HP);
    float* s_red = (float*)(sm + OFF_RED);

    // ---- stage small arrays ----
    for (int i = tid; i < DIM; i += 256) {
        s_b1[i] = b1[i];
        s_vw[i] = Vw[i];
        s_hp[i]       = g_hproj[(size_t)bidx0 * DIM + i];
        s_hp[DIM + i] = (bidx0 + 1 < BS) ? g_hproj[(size_t)(bidx0 + 1) * DIM + i] : 0.0f;
    }

    // ---- convert A slab (64 x 512 fp32) into smem hi/lo bf16, full K resident ----
    const float4* Av = (const float4*)A;
    for (int i = tid; i < MTILE * 128; i += 256) {       // 128 float4 per row
        int r = i >> 7, c4 = i & 127;
        float4 x = Av[(size_t)(m0 + r) * 128 + c4];
        split_store4(x, a_hi + r * APITCH + c4 * 4, a_lo + r * APITCH + c4 * 4);
    }
    __syncthreads();

    // ---- precompute ldmatrix lane addresses ----
    const int a_row = wm * 16 + (lane & 15);
    const int a_k   = (lane >> 4) * 8;
    const uint32_t ah_addr = smbase + OFF_AH + (uint32_t)(a_row * APITCH + a_k) * 2;
    const uint32_t al_addr = smbase + OFF_AL + (uint32_t)(a_row * APITCH + a_k) * 2;

    const int b_n = (lane & 7) + ((lane >> 4) & 1) * 8;
    const int b_k = ((lane >> 3) & 1) * 8;
    const uint32_t bq = (uint32_t)((wn * 32 + b_n) * BPITCH + b_k) * 2;   // p=0 offset
    // [buf][split] buffers
    uint32_t bhi_addr[2], blo_addr[2];
    bhi_addr[0] = smbase + OFF_B + 0 * BSZ + bq;
    blo_addr[0] = smbase + OFF_B + 1 * BSZ + bq;
    bhi_addr[1] = smbase + OFF_B + 2 * BSZ + bq;
    blo_addr[1] = smbase + OFF_B + 3 * BSZ + bq;

    // B conversion store indices (per thread, 4 float4 per chunk)
    const int brow0 = tid >> 4;         // advances by 16 per t
    const int bc4   = tid & 15;

    const float4* W1v = (const float4*)W1;

    // epilogue row info (constant across nb)
    const int r0g  = wm * 16 + (lane >> 2);
    const int m_r0 = m0 + r0g;
    const int m_r1 = m_r0 + 8;
    const float* hp0 = s_hp + (m_r0 / SEQ - bidx0) * DIM;
    const float* hp1 = s_hp + (m_r1 / SEQ - bidx0) * DIM;

    float rs0 = 0.0f, rs1 = 0.0f;

    for (int nb = 0; nb < 8; ++nb) {
        const int n0 = nb * 64;

        float acc[4][4];
        #pragma unroll
        for (int f = 0; f < 4; ++f)
            #pragma unroll
            for (int e = 0; e < 4; ++e) acc[f][e] = 0.0f;

        // preload chunk 0 into buf 0
        {
            float4 rb[4];
            #pragma unroll
            for (int t = 0; t < 4; ++t)
                rb[t] = W1v[(size_t)(n0 + brow0 + t * 16) * 128 + bc4];
            __nv_bfloat16* bh = (__nv_bfloat16*)(sm + OFF_B + 0 * BSZ);
            __nv_bfloat16* bl = (__nv_bfloat16*)(sm + OFF_B + 1 * BSZ);
            #pragma unroll
            for (int t = 0; t < 4; ++t) {
                int r = brow0 + t * 16;
                split_store4(rb[t], bh + r * BPITCH + bc4 * 4, bl + r * BPITCH + bc4 * 4);
            }
            __syncthreads();
        }

        for (int kc = 0; kc < 8; ++kc) {
            const int cur = kc & 1;

            // issue global loads for next chunk early (hidden under MMA)
            float4 rb[4];
            if (kc < 7) {
                #pragma unroll
                for (int t = 0; t < 4; ++t)
                    rb[t] = W1v[(size_t)(n0 + brow0 + t * 16) * 128 + (kc + 1) * 16 + bc4];
            }

            #pragma unroll
            for (int ks = 0; ks < 4; ++ks) {
                const uint32_t koff = (uint32_t)(kc * 64 + ks * 16) * 2;
                const uint32_t bko  = (uint32_t)(ks * 16) * 2;
                uint32_t ah[4], al[4], bh[8], bl[8];
                ldsm4(ah, ah_addr + koff);
                ldsm4(al, al_addr + koff);
                ldsm4(bh,     bhi_addr[cur] + bko);
                ldsm4(bh + 4, bhi_addr[cur] + 16 * BPITCH * 2 + bko);
                ldsm4(bl,     blo_addr[cur] + bko);
                ldsm4(bl + 4, blo_addr[cur] + 16 * BPITCH * 2 + bko);
                #pragma unroll
                for (int f = 0; f < 4; ++f) mma16816(acc[f], ah, bh[2*f], bh[2*f+1]);
                #pragma unroll
                for (int f = 0; f < 4; ++f) mma16816(acc[f], ah, bl[2*f], bl[2*f+1]);
                #pragma unroll
                for (int f = 0; f < 4; ++f) mma16816(acc[f], al, bh[2*f], bh[2*f+1]);
            }

            if (kc < 7) {
                const int nxt = (kc + 1) & 1;
                __nv_bfloat16* bh = (__nv_bfloat16*)(sm + OFF_B + (nxt * 2 + 0) * BSZ);
                __nv_bfloat16* bl = (__nv_bfloat16*)(sm + OFF_B + (nxt * 2 + 1) * BSZ);
                #pragma unroll
                for (int t = 0; t < 4; ++t) {
                    int r = brow0 + t * 16;
                    split_store4(rb[t], bh + r * BPITCH + bc4 * 4, bl + r * BPITCH + bc4 * 4);
                }
            }
            __syncthreads();
        }

        // ---- fused epilogue for this N-tile ----
        #pragma unroll
        for (int f = 0; f < 4; ++f) {
            const int nbase = n0 + wn * 32 + f * 8 + 2 * (lane & 3);
            #pragma unroll
            for (int e = 0; e < 2; ++e) {
                const int n = nbase + e;
                const float bb = s_b1[n];
                const float vv = s_vw[n];
                float x0 = fmaxf(acc[f][e] + bb, 0.0f) + hp0[n];
                rs0 += vv * tanh_pos(x0);
                float x1 = fmaxf(acc[f][2 + e] + bb, 0.0f) + hp1[n];
                rs1 += vv * tanh_pos(x1);
            }
        }
    }

    // ---- deterministic reduction: quad butterfly then 2-way via smem ----
    rs0 += __shfl_xor_sync(0xffffffffu, rs0, 1);
    rs0 += __shfl_xor_sync(0xffffffffu, rs0, 2);
    rs1 += __shfl_xor_sync(0xffffffffu, rs1, 1);
    rs1 += __shfl_xor_sync(0xffffffffu, rs1, 2);
    if ((lane & 3) == 0) {
        s_red[wn * 64 + r0g]     = rs0;
        s_red[wn * 64 + r0g + 8] = rs1;
    }
    __syncthreads();
    if (tid < 64)
        g_score[m0 + tid] = s_red[tid] + s_red[64 + tid] + Vb[0];
}

// ===================== hproj kernel (proven, 74us) =====================
#define TM 128
#define TN 128
#define KS 16
__global__ void __launch_bounds__(256) hproj_kernel(
    const float* __restrict__ A,    // hidden [1024,512]
    const float* __restrict__ B,    // W2_w   [512,512]
    const float* __restrict__ bias) // W2_b   [512]
{
    __shared__ float As[KS][TM + 4];
    __shared__ float Bs[KS][TN + 4];

    const int tid = threadIdx.x;
    const int tx  = tid & 15;
    const int ty  = tid >> 4;
    const int m0  = blockIdx.x * TM;
    const int n0  = blockIdx.y * TN;

    float acc[8][8];
    #pragma unroll
    for (int i = 0; i < 8; ++i)
        #pragma unroll
        for (int j = 0; j < 8; ++j) acc[i][j] = 0.f;

    for (int kk = 0; kk < DIM; kk += KS) {
        __syncthreads();
        #pragma unroll
        for (int t = 0; t < 2; ++t) {
            int f   = tid + t * 256;
            int row = f >> 2, seg = f & 3;
            float4 v = *reinterpret_cast<const float4*>(A + (size_t)(m0 + row) * DIM + kk + seg * 4);
            As[seg*4+0][row] = v.x; As[seg*4+1][row] = v.y;
            As[seg*4+2][row] = v.z; As[seg*4+3][row] = v.w;
            float4 w = *reinterpret_cast<const float4*>(B + (size_t)(n0 + row) * DIM + kk + seg * 4);
            Bs[seg*4+0][row] = w.x; Bs[seg*4+1][row] = w.y;
            Bs[seg*4+2][row] = w.z; Bs[seg*4+3][row] = w.w;
        }
        __syncthreads();
        #pragma unroll
        for (int k = 0; k < KS; ++k) {
            float a[8], b[8];
            const float4* ap = reinterpret_cast<const float4*>(&As[k][ty * 8]);
            const float4* bp = reinterpret_cast<const float4*>(&Bs[k][tx * 8]);
            float4 a0 = ap[0], a1 = ap[1];
            float4 b0 = bp[0], b1 = bp[1];
            a[0]=a0.x; a[1]=a0.y; a[2]=a0.z; a[3]=a0.w;
            a[4]=a1.x; a[5]=a1.y; a[6]=a1.z; a[7]=a1.w;
            b[0]=b0.x; b[1]=b0.y; b[2]=b0.z; b[3]=b0.w;
            b[4]=b1.x; b[5]=b1.y; b[6]=b1.z; b[7]=b1.w;
            #pragma unroll
            for (int i = 0; i < 8; ++i)
                #pragma unroll
                for (int j = 0; j < 8; ++j)
                    acc[i][j] += a[i] * b[j];
        }
    }

    #pragma unroll
    for (int i = 0; i < 8; ++i) {
        int m = m0 + ty * 8 + i;
        #pragma unroll
        for (int j = 0; j < 8; ++j) {
            int n = n0 + tx * 8 + j;
            float v = acc[i][j] + bias[n];
            g_hproj[(size_t)m * DIM + n] = v > 0.f ? v : 0.f;
        }
    }
}

// ===================== softmax + context (proven) =====================
__global__ void __launch_bounds__(512) softmax_ctx_kernel(
    const float* __restrict__ features,
    float* __restrict__ out)
{
    __shared__ float w[SEQ];
    __shared__ float red[512];

    const int b   = blockIdx.x;
    const int tid = threadIdx.x;

    float sc = (tid < SEQ) ? g_score[b * SEQ + tid] : -3.4e38f;
    red[tid] = sc;
    __syncthreads();
    #pragma unroll
    for (int off = 256; off > 0; off >>= 1) {
        if (tid < off) red[tid] = fmaxf(red[tid], red[tid + off]);
        __syncthreads();
    }
    float mx = red[0];
    __syncthreads();

    float e = (tid < SEQ) ? expf(sc - mx) : 0.f;
    red[tid] = e;
    __syncthreads();
    #pragma unroll
    for (int off = 256; off > 0; off >>= 1) {
        if (tid < off) red[tid] += red[tid + off];
        __syncthreads();
    }
    float inv = 1.f / red[0];

    float wt = e * inv;
    if (tid < SEQ) {
        w[tid] = wt;
        out[(size_t)BS * DIM + (size_t)b * SEQ + tid] = wt;
    }
    __syncthreads();

    float acc = 0.f;
    const float* fb = features + (size_t)b * SEQ * DIM + tid;
    #pragma unroll 4
    for (int s = 0; s < SEQ; ++s)
        acc += w[s] * fb[(size_t)s * DIM];
    out[(size_t)b * DIM + tid] = acc;
}

// ===================== launch =====================
extern "C" void kernel_launch(void* const* d_in, const int* in_sizes, int n_in,
                              void* d_out, int out_size)
{
    const float* hidden   = (const float*)d_in[0];
    const float* features = (const float*)d_in[1];
    const float* W1_w     = (const float*)d_in[2];
    const float* W1_b     = (const float*)d_in[3];
    const float* W2_w     = (const float*)d_in[4];
    const float* W2_b     = (const float*)d_in[5];
    const float* V_w      = (const float*)d_in[6];
    const float* V_b      = (const float*)d_in[7];
    float* out = (float*)d_out;

    cudaFuncSetAttribute(score_mma_kernel,
                         cudaFuncAttributeMaxDynamicSharedMemorySize, SMEM_BYTES);

    hproj_kernel<<<dim3(BS / TM, DIM / TN), 256>>>(hidden, W2_w, W2_b);
    score_mma_kernel<<<MTOT / MTILE, 256, SMEM_BYTES>>>(features, W1_w, W1_b, V_w, V_b);
    softmax_ctx_kernel<<<BS, 512>>>(features, out);
}

// round 4
// speedup vs baseline: 1.9863x; 1.0496x over previous
#include <cuda_runtime.h>
#include <cuda_bf16.h>
#include <cuda_fp16.h>
#include <math.h>
#include <stdint.h>

#define BS   1024
#define SEQ  360
#define DIM  512
#define MTOT (BS*SEQ)

// ===================== scratch =====================
__device__ float g_hproj[BS * DIM];                 // relu(hidden @ W2^T + b2)
__device__ float g_score[BS * SEQ];                 // pre-softmax scores
__device__ __nv_bfloat16 g_w1h[DIM * DIM];          // W1 bf16 hi
__device__ __nv_bfloat16 g_w1l[DIM * DIM];          // W1 bf16 lo (residual)

// ===================== helpers =====================
__device__ __forceinline__ uint32_t smem_u32(const void* p) {
    uint32_t a;
    asm("{ .reg .u64 t; cvta.to.shared.u64 t, %1; cvt.u32.u64 %0, t; }" : "=r"(a) : "l"(p));
    return a;
}

__device__ __forceinline__ void ldsm4(uint32_t* r, uint32_t addr) {
    asm volatile("ldmatrix.sync.aligned.m8n8.x4.shared.b16 {%0,%1,%2,%3}, [%4];"
                 : "=r"(r[0]), "=r"(r[1]), "=r"(r[2]), "=r"(r[3]) : "r"(addr));
}

__device__ __forceinline__ void mma16816_bf16(float* c, const uint32_t* a, uint32_t b0, uint32_t b1) {
    asm volatile("mma.sync.aligned.m16n8k16.row.col.f32.bf16.bf16.f32 "
                 "{%0,%1,%2,%3}, {%4,%5,%6,%7}, {%8,%9}, {%0,%1,%2,%3};"
                 : "+f"(c[0]), "+f"(c[1]), "+f"(c[2]), "+f"(c[3])
                 : "r"(a[0]), "r"(a[1]), "r"(a[2]), "r"(a[3]), "r"(b0), "r"(b1));
}

__device__ __forceinline__ void mma16816_f16(float* c, uint32_t a0, uint32_t a1,
                                             uint32_t a2, uint32_t a3,
                                             uint32_t b0, uint32_t b1) {
    asm volatile("mma.sync.aligned.m16n8k16.row.col.f32.f16.f16.f32 "
                 "{%0,%1,%2,%3}, {%4,%5,%6,%7}, {%8,%9}, {%0,%1,%2,%3};"
                 : "+f"(c[0]), "+f"(c[1]), "+f"(c[2]), "+f"(c[3])
                 : "r"(a0), "r"(a1), "r"(a2), "r"(a3), "r"(b0), "r"(b1));
}

__device__ __forceinline__ uint32_t pk2(__nv_bfloat16 a, __nv_bfloat16 b) {
    return (uint32_t)__bfloat16_as_ushort(a) | ((uint32_t)__bfloat16_as_ushort(b) << 16);
}

// split fp32x4 -> bf16 hi (round) + bf16 lo (residual)
__device__ __forceinline__ void split_store4(float4 x, __nv_bfloat16* ph, __nv_bfloat16* pl) {
    __nv_bfloat16 h0 = __float2bfloat16(x.x), h1 = __float2bfloat16(x.y);
    __nv_bfloat16 h2 = __float2bfloat16(x.z), h3 = __float2bfloat16(x.w);
    float r0 = x.x - __bfloat162float(h0), r1 = x.y - __bfloat162float(h1);
    float r2 = x.z - __bfloat162float(h2), r3 = x.w - __bfloat162float(h3);
    uint2 uh, ul;
    uh.x = pk2(h0, h1); uh.y = pk2(h2, h3);
    ul.x = pk2(__float2bfloat16(r0), __float2bfloat16(r1));
    ul.y = pk2(__float2bfloat16(r2), __float2bfloat16(r3));
    *(uint2*)ph = uh;
    *(uint2*)pl = ul;
}

// f16x2 epilogue primitives
__device__ __forceinline__ uint32_t cvt_f16x2(float hi, float lo) {
    uint32_t d; asm("cvt.rn.f16x2.f32 %0, %1, %2;" : "=r"(d) : "f"(hi), "f"(lo)); return d;
}
__device__ __forceinline__ uint32_t hmax2_0(uint32_t x) {
    uint32_t d; asm("max.f16x2 %0, %1, %2;" : "=r"(d) : "r"(x), "r"(0u)); return d;
}
__device__ __forceinline__ uint32_t hadd2(uint32_t a, uint32_t b) {
    uint32_t d; asm("add.f16x2 %0, %1, %2;" : "=r"(d) : "r"(a), "r"(b)); return d;
}
__device__ __forceinline__ uint32_t htanh2(uint32_t x) {
    uint32_t d; asm("tanh.approx.f16x2 %0, %1;" : "=r"(d) : "r"(x)); return d;
}
__device__ __forceinline__ uint32_t pkh2(float lo, float hi) {
    __half2 h = __floats2half2_rn(lo, hi);   // .x = lo
    return *(uint32_t*)&h;
}

// ===================== prep: W1 -> bf16 hi/lo (once) =====================
__global__ void __launch_bounds__(256) prep_w1_kernel(const float* __restrict__ W1) {
    int i = blockIdx.x * 256 + threadIdx.x;        // 65536 float4s
    float4 x = ((const float4*)W1)[i];
    split_store4(x, g_w1h + (size_t)i * 4, g_w1l + (size_t)i * 4);
}

// ===================== score kernel =====================
#define MTILE  64
#define APITCH 520                 // bf16 elems; 1040B, mod 128 = 16
#define BPITCH 72                  // 144B, mod 128 = 16
#define BSZ    (64*BPITCH*2)       // 9216 B per split buffer

#define OFF_AH  0
#define OFF_AL  (MTILE*APITCH*2)             // 66560
#define OFF_B   (2*MTILE*APITCH*2)           // 133120 ; [buf][split] x BSZ
#define OFF_B1  (OFF_B + 4*BSZ)              // 169984 (512 f32)
#define OFF_V2H (OFF_B1 + 2048)              // 172032 (256 u32)
#define OFF_V2L (OFF_V2H + 1024)             // 173056 (256 u32)
#define OFF_HP2 (OFF_V2L + 1024)             // 174080 (2 x 256 u32)
#define OFF_RED (OFF_HP2 + 2048)             // 176128 (256 f32)
#define SMEM_BYTES (OFF_RED + 1024)          // 177152

__global__ void __launch_bounds__(256, 1)
score_mma_kernel(const float* __restrict__ A,   // features [368640, 512]
                 const float* __restrict__ b1,  // [512]
                 const float* __restrict__ Vw,  // [512]
                 const float* __restrict__ Vb)  // [1]
{
    extern __shared__ char sm[];
    const uint32_t smbase = smem_u32(sm);

    const int tid  = threadIdx.x;
    const int lane = tid & 31;
    const int wid  = tid >> 5;
    const int wm   = wid & 3;       // 4 m-subtiles of 16
    const int wn   = wid >> 2;      // 2 n-subtiles of 32
    const int m0   = blockIdx.x * MTILE;
    const int bidx0 = m0 / SEQ;

    __nv_bfloat16* a_hi = (__nv_bfloat16*)(sm + OFF_AH);
    __nv_bfloat16* a_lo = (__nv_bfloat16*)(sm + OFF_AL);
    float*    s_b1  = (float*)(sm + OFF_B1);
    uint32_t* s_v2h = (uint32_t*)(sm + OFF_V2H);
    uint32_t* s_v2l = (uint32_t*)(sm + OFF_V2L);
    uint32_t* s_hp2 = (uint32_t*)(sm + OFF_HP2);
    float*    s_red = (float*)(sm + OFF_RED);

    // ---- stage tables ----
    for (int i = tid; i < DIM; i += 256) s_b1[i] = b1[i];
    if (tid < 256) {
        float2 vv = ((const float2*)Vw)[tid];
        float vh0 = __half2float(__float2half_rn(vv.x));
        float vh1 = __half2float(__float2half_rn(vv.y));
        s_v2h[tid] = pkh2(vh0, vh1);
        s_v2l[tid] = pkh2(vv.x - vh0, vv.y - vh1);
        float2 h0 = ((const float2*)(g_hproj + (size_t)bidx0 * DIM))[tid];
        s_hp2[tid] = pkh2(h0.x, h0.y);
        float2 h1 = make_float2(0.f, 0.f);
        if (bidx0 + 1 < BS)
            h1 = ((const float2*)(g_hproj + (size_t)(bidx0 + 1) * DIM))[tid];
        s_hp2[256 + tid] = pkh2(h1.x, h1.y);
    }

    // ---- convert A slab (64 x 512 fp32) into smem hi/lo bf16 ----
    const float4* Av = (const float4*)A;
    for (int i = tid; i < MTILE * 128; i += 256) {
        int r = i >> 7, c4 = i & 127;
        float4 x = Av[(size_t)(m0 + r) * 128 + c4];
        split_store4(x, a_hi + r * APITCH + c4 * 4, a_lo + r * APITCH + c4 * 4);
    }
    __syncthreads();

    // ---- ldmatrix lane addresses ----
    const int a_row = wm * 16 + (lane & 15);
    const int a_k   = (lane >> 4) * 8;
    const uint32_t ah_addr = smbase + OFF_AH + (uint32_t)(a_row * APITCH + a_k) * 2;
    const uint32_t al_addr = smbase + OFF_AL + (uint32_t)(a_row * APITCH + a_k) * 2;

    const int b_n = (lane & 7) + ((lane >> 4) & 1) * 8;
    const int b_k = ((lane >> 3) & 1) * 8;
    const uint32_t bq = (uint32_t)((wn * 32 + b_n) * BPITCH + b_k) * 2;
    uint32_t bhi_addr[2], blo_addr[2];
    bhi_addr[0] = smbase + OFF_B + 0 * BSZ + bq;
    blo_addr[0] = smbase + OFF_B + 1 * BSZ + bq;
    bhi_addr[1] = smbase + OFF_B + 2 * BSZ + bq;
    blo_addr[1] = smbase + OFF_B + 3 * BSZ + bq;

    // B copy indices (pre-converted bf16 from global, pure 16B copies)
    const int crow = tid >> 2;            // 0..63
    const int cseg = (tid & 3) * 2;       // 0,2,4,6 (uint4 units of 8 bf16)
    const uint4* gw1h = (const uint4*)g_w1h;   // row stride 512 bf16 = 64 uint4
    const uint4* gw1l = (const uint4*)g_w1l;

    // epilogue row info
    const int g      = lane >> 2;
    const int t      = lane & 3;
    const int r0g    = wm * 16 + g;
    const int rowsel0 = ((m0 + r0g) / SEQ) - bidx0;
    const int rowsel1 = ((m0 + r0g + 8) / SEQ) - bidx0;

    float acc2[4] = {0.f, 0.f, 0.f, 0.f};   // GEMM2 (V-dot) accumulators

    for (int nb = 0; nb < 8; ++nb) {
        const int n0 = nb * 64;
        const int pbase = ((n0 + wn * 32) >> 1) + t;   // f16x2-pair index base

        // ---- init acc with bias ----
        float acc[4][4];
        {
            const float2* b1v = (const float2*)s_b1;
            int bb0 = ((n0 + wn * 32) >> 1) + t;
            #pragma unroll
            for (int f = 0; f < 4; ++f) {
                float2 bb = b1v[bb0 + f * 4];
                acc[f][0] = bb.x; acc[f][1] = bb.y;
                acc[f][2] = bb.x; acc[f][3] = bb.y;
            }
        }

        // ---- preload chunk 0 into buf 0 ----
        {
            size_t gi = (size_t)(n0 + crow) * 64 + cseg;
            uint4 h0 = gw1h[gi], h1 = gw1h[gi + 1];
            uint4 l0 = gw1l[gi], l1 = gw1l[gi + 1];
            uint4* bh = (uint4*)(sm + OFF_B + 0 * BSZ);
            uint4* bl = (uint4*)(sm + OFF_B + 1 * BSZ);
            int so = crow * 9 + cseg;
            bh[so] = h0; bh[so + 1] = h1;
            bl[so] = l0; bl[so + 1] = l1;
            __syncthreads();
        }

        for (int kc = 0; kc < 8; ++kc) {
            const int cur = kc & 1;

            // issue next chunk's global loads early
            uint4 h0, h1, l0, l1;
            if (kc < 7) {
                size_t gi = (size_t)(n0 + crow) * 64 + (kc + 1) * 8 + cseg;
                h0 = gw1h[gi]; h1 = gw1h[gi + 1];
                l0 = gw1l[gi]; l1 = gw1l[gi + 1];
            }

            #pragma unroll
            for (int ks = 0; ks < 4; ++ks) {
                const uint32_t koff = (uint32_t)(kc * 64 + ks * 16) * 2;
                const uint32_t bko  = (uint32_t)(ks * 16) * 2;
                uint32_t ah[4], al[4], bh[8], bl[8];
                ldsm4(ah, ah_addr + koff);
                ldsm4(al, al_addr + koff);
                ldsm4(bh,     bhi_addr[cur] + bko);
                ldsm4(bh + 4, bhi_addr[cur] + 16 * BPITCH * 2 + bko);
                ldsm4(bl,     blo_addr[cur] + bko);
                ldsm4(bl + 4, blo_addr[cur] + 16 * BPITCH * 2 + bko);
                #pragma unroll
                for (int f = 0; f < 4; ++f) mma16816_bf16(acc[f], ah, bh[2*f], bh[2*f+1]);
                #pragma unroll
                for (int f = 0; f < 4; ++f) mma16816_bf16(acc[f], ah, bl[2*f], bl[2*f+1]);
                #pragma unroll
                for (int f = 0; f < 4; ++f) mma16816_bf16(acc[f], al, bh[2*f], bh[2*f+1]);
            }

            if (kc < 7) {
                const int nxt = (kc + 1) & 1;
                uint4* bh = (uint4*)(sm + OFF_B + (nxt * 2 + 0) * BSZ);
                uint4* bl = (uint4*)(sm + OFF_B + (nxt * 2 + 1) * BSZ);
                int so = crow * 9 + cseg;
                bh[so] = h0; bh[so + 1] = h1;
                bl[so] = l0; bl[so + 1] = l1;
            }
            __syncthreads();
        }

        // ---- fused epilogue: relu+hp+tanh in f16x2, V-dot via tensor pipe ----
        uint32_t tf[4][2];
        #pragma unroll
        for (int f = 0; f < 4; ++f) {
            uint32_t hpa = s_hp2[rowsel0 * 256 + pbase + f * 4];
            uint32_t hpb = s_hp2[rowsel1 * 256 + pbase + f * 4];
            uint32_t x0 = cvt_f16x2(acc[f][1], acc[f][0]);   // rows g
            uint32_t x1 = cvt_f16x2(acc[f][3], acc[f][2]);   // rows g+8
            x0 = hadd2(hmax2_0(x0), hpa);
            x1 = hadd2(hmax2_0(x1), hpb);
            tf[f][0] = htanh2(x0);
            tf[f][1] = htanh2(x1);
        }
        #pragma unroll
        for (int F = 0; F < 2; ++F) {
            uint32_t b0h = s_v2h[pbase + F * 8];
            uint32_t b1h = s_v2h[pbase + F * 8 + 4];
            uint32_t b0l = s_v2l[pbase + F * 8];
            uint32_t b1l = s_v2l[pbase + F * 8 + 4];
            mma16816_f16(acc2, tf[2*F][0], tf[2*F][1], tf[2*F+1][0], tf[2*F+1][1], b0h, b1h);
            mma16816_f16(acc2, tf[2*F][0], tf[2*F][1], tf[2*F+1][0], tf[2*F+1][1], b0l, b1l);
        }
    }

    // ---- deterministic final reduction ----
    if (t == 0) {
        s_red[wn * 128 + r0g]     = acc2[0];   // row g
        s_red[wn * 128 + r0g + 8] = acc2[2];   // row g+8
    }
    __syncthreads();
    if (tid < 64)
        g_score[m0 + tid] = s_red[tid] + s_red[128 + tid] + Vb[0];
}

// ===================== hproj kernel: 64x64 tiles, 128 CTAs =====================
__global__ void __launch_bounds__(256) hproj_kernel(
    const float* __restrict__ A,    // hidden [1024,512]
    const float* __restrict__ B,    // W2_w   [512,512]
    const float* __restrict__ bias) // W2_b   [512]
{
    __shared__ float As[16][68];
    __shared__ float Bs[16][68];

    const int tid = threadIdx.x;
    const int tx  = tid & 15;
    const int ty  = tid >> 4;
    const int m0  = blockIdx.x * 64;
    const int n0  = blockIdx.y * 64;

    float acc[4][4];
    #pragma unroll
    for (int i = 0; i < 4; ++i)
        #pragma unroll
        for (int j = 0; j < 4; ++j) acc[i][j] = 0.f;

    const int lrow = tid >> 2, lseg = tid & 3;

    for (int kk = 0; kk < DIM; kk += 16) {
        __syncthreads();
        float4 v = *reinterpret_cast<const float4*>(A + (size_t)(m0 + lrow) * DIM + kk + lseg * 4);
        As[lseg*4+0][lrow] = v.x; As[lseg*4+1][lrow] = v.y;
        As[lseg*4+2][lrow] = v.z; As[lseg*4+3][lrow] = v.w;
        float4 w = *reinterpret_cast<const float4*>(B + (size_t)(n0 + lrow) * DIM + kk + lseg * 4);
        Bs[lseg*4+0][lrow] = w.x; Bs[lseg*4+1][lrow] = w.y;
        Bs[lseg*4+2][lrow] = w.z; Bs[lseg*4+3][lrow] = w.w;
        __syncthreads();
        #pragma unroll
        for (int k = 0; k < 16; ++k) {
            float4 a4 = *reinterpret_cast<const float4*>(&As[k][ty * 4]);
            float4 b4 = *reinterpret_cast<const float4*>(&Bs[k][tx * 4]);
            float a[4] = {a4.x, a4.y, a4.z, a4.w};
            float b[4] = {b4.x, b4.y, b4.z, b4.w};
            #pragma unroll
            for (int i = 0; i < 4; ++i)
                #pragma unroll
                for (int j = 0; j < 4; ++j)
                    acc[i][j] += a[i] * b[j];
        }
    }

    #pragma unroll
    for (int i = 0; i < 4; ++i) {
        int m = m0 + ty * 4 + i;
        #pragma unroll
        for (int j = 0; j < 4; ++j) {
            int n = n0 + tx * 4 + j;
            float v = acc[i][j] + bias[n];
            g_hproj[(size_t)m * DIM + n] = v > 0.f ? v : 0.f;
        }
    }
}

// ===================== softmax + context =====================
__global__ void __launch_bounds__(512) softmax_ctx_kernel(
    const float* __restrict__ features,
    float* __restrict__ out)
{
    __shared__ float w[SEQ];
    __shared__ float red[512];

    const int b   = blockIdx.x;
    const int tid = threadIdx.x;

    float sc = (tid < SEQ) ? g_score[b * SEQ + tid] : -3.4e38f;
    red[tid] = sc;
    __syncthreads();
    #pragma unroll
    for (int off = 256; off > 0; off >>= 1) {
        if (tid < off) red[tid] = fmaxf(red[tid], red[tid + off]);
        __syncthreads();
    }
    float mx = red[0];
    __syncthreads();

    float e = (tid < SEQ) ? expf(sc - mx) : 0.f;
    red[tid] = e;
    __syncthreads();
    #pragma unroll
    for (int off = 256; off > 0; off >>= 1) {
        if (tid < off) red[tid] += red[tid + off];
        __syncthreads();
    }
    float inv = 1.f / red[0];

    float wt = e * inv;
    if (tid < SEQ) {
        w[tid] = wt;
        out[(size_t)BS * DIM + (size_t)b * SEQ + tid] = wt;
    }
    __syncthreads();

    float acc = 0.f;
    const float* fb = features + (size_t)b * SEQ * DIM + tid;
    #pragma unroll 4
    for (int s = 0; s < SEQ; ++s)
        acc += w[s] * fb[(size_t)s * DIM];
    out[(size_t)b * DIM + tid] = acc;
}

// ===================== launch =====================
extern "C" void kernel_launch(void* const* d_in, const int* in_sizes, int n_in,
                              void* d_out, int out_size)
{
    const float* hidden   = (const float*)d_in[0];
    const float* features = (const float*)d_in[1];
    const float* W1_w     = (const float*)d_in[2];
    const float* W1_b     = (const float*)d_in[3];
    const float* W2_w     = (const float*)d_in[4];
    const float* W2_b     = (const float*)d_in[5];
    const float* V_w      = (const float*)d_in[6];
    const float* V_b      = (const float*)d_in[7];
    float* out = (float*)d_out;

    cudaFuncSetAttribute(score_mma_kernel,
                         cudaFuncAttributeMaxDynamicSharedMemorySize, SMEM_BYTES);

    prep_w1_kernel<<<256, 256>>>(W1_w);
    hproj_kernel<<<dim3(16, 8), 256>>>(hidden, W2_w, W2_b);
    score_mma_kernel<<<MTOT / MTILE, 256, SMEM_BYTES>>>(features, W1_b, V_w, V_b);
    softmax_ctx_kernel<<<BS, 512>>>(features, out);
}

// round 5
// speedup vs baseline: 4.0394x; 2.0336x over previous
#include <cuda_runtime.h>
#include <cuda_bf16.h>
#include <cuda_fp16.h>
#include <math.h>
#include <stdint.h>

#define BS   1024
#define SEQ  360
#define DIM  512
#define MTOT (BS*SEQ)

// ===================== scratch =====================
__device__ float g_hproj[BS * DIM];          // relu(hidden @ W2^T + b2)
__device__ float g_score[BS * SEQ];          // pre-softmax scores
__device__ __half g_w1f[DIM * DIM];          // W1 fp16

// ===================== helpers =====================
__device__ __forceinline__ uint32_t smem_u32(const void* p) {
    uint32_t a;
    asm("{ .reg .u64 t; cvta.to.shared.u64 t, %1; cvt.u32.u64 %0, t; }" : "=r"(a) : "l"(p));
    return a;
}

__device__ __forceinline__ void ldsm4(uint32_t* r, uint32_t addr) {
    asm volatile("ldmatrix.sync.aligned.m8n8.x4.shared.b16 {%0,%1,%2,%3}, [%4];"
                 : "=r"(r[0]), "=r"(r[1]), "=r"(r[2]), "=r"(r[3]) : "r"(addr));
}

__device__ __forceinline__ void mma16816_f16(float* c, uint32_t a0, uint32_t a1,
                                             uint32_t a2, uint32_t a3,
                                             uint32_t b0, uint32_t b1) {
    asm volatile("mma.sync.aligned.m16n8k16.row.col.f32.f16.f16.f32 "
                 "{%0,%1,%2,%3}, {%4,%5,%6,%7}, {%8,%9}, {%0,%1,%2,%3};"
                 : "+f"(c[0]), "+f"(c[1]), "+f"(c[2]), "+f"(c[3])
                 : "r"(a0), "r"(a1), "r"(a2), "r"(a3), "r"(b0), "r"(b1));
}

// f16x2 primitives
__device__ __forceinline__ uint32_t cvt_f16x2(float hi, float lo) {
    uint32_t d; asm("cvt.rn.f16x2.f32 %0, %1, %2;" : "=r"(d) : "f"(hi), "f"(lo)); return d;
}
__device__ __forceinline__ uint32_t hmax2_0(uint32_t x) {
    uint32_t d; asm("max.f16x2 %0, %1, %2;" : "=r"(d) : "r"(x), "r"(0u)); return d;
}
__device__ __forceinline__ uint32_t hadd2(uint32_t a, uint32_t b) {
    uint32_t d; asm("add.f16x2 %0, %1, %2;" : "=r"(d) : "r"(a), "r"(b)); return d;
}
__device__ __forceinline__ uint32_t htanh2(uint32_t x) {
    uint32_t d; asm("tanh.approx.f16x2 %0, %1;" : "=r"(d) : "r"(x)); return d;
}
__device__ __forceinline__ uint32_t pkh2(float lo, float hi) {
    __half2 h = __floats2half2_rn(lo, hi);   // .x = lo
    return *(uint32_t*)&h;
}
__device__ __forceinline__ uint32_t cvt4_f16(float4 x, uint32_t& hi2) {
    // returns packed {x.x,x.y}, sets hi2 = {x.z,x.w}
    hi2 = pkh2(x.z, x.w);
    return pkh2(x.x, x.y);
}

// ===================== prep: W1 -> fp16 (once) =====================
__global__ void __launch_bounds__(256) prep_w1_kernel(const float* __restrict__ W1) {
    int i = blockIdx.x * 256 + threadIdx.x;        // 65536 float4s
    float4 x = ((const float4*)W1)[i];
    uint32_t hi, lo = cvt4_f16(x, hi);
    uint2 v; v.x = lo; v.y = hi;
    *(uint2*)(g_w1f + (size_t)i * 4) = v;
}

// ===================== score kernel =====================
#define MTILE  64
#define APITCH 520                 // fp16 elems; 1040B, mod 128 = 16 -> conflict-free ldmatrix
#define BPITCH 72                  // 144B, mod 128 = 16
#define BSZ    (64*BPITCH*2)       // 9216 B per B buffer

#define OFF_A   0
#define OFF_B   (MTILE*APITCH*2)             // 66560 ; 2 bufs x BSZ
#define OFF_B1  (OFF_B + 2*BSZ)              // 84992 (512 f32)
#define OFF_V2H (OFF_B1 + 2048)              // 87040 (256 u32)
#define OFF_V2L (OFF_V2H + 1024)             // 88064 (256 u32)
#define OFF_HP2 (OFF_V2L + 1024)             // 89088 (2 x 256 u32)
#define OFF_RED (OFF_HP2 + 2048)             // 91136 (256 f32)
#define SMEM_BYTES (OFF_RED + 1024)          // 92160

__global__ void __launch_bounds__(256, 2)
score_mma_kernel(const float* __restrict__ A,   // features [368640, 512]
                 const float* __restrict__ b1,  // [512]
                 const float* __restrict__ Vw,  // [512]
                 const float* __restrict__ Vb)  // [1]
{
    extern __shared__ char sm[];
    const uint32_t smbase = smem_u32(sm);

    const int tid  = threadIdx.x;
    const int lane = tid & 31;
    const int wid  = tid >> 5;
    const int wm   = wid & 3;       // 4 m-subtiles of 16
    const int wn   = wid >> 2;      // 2 n-subtiles of 32
    const int m0   = blockIdx.x * MTILE;
    const int bidx0 = m0 / SEQ;

    __half*   a_f   = (__half*)(sm + OFF_A);
    float*    s_b1  = (float*)(sm + OFF_B1);
    uint32_t* s_v2h = (uint32_t*)(sm + OFF_V2H);
    uint32_t* s_v2l = (uint32_t*)(sm + OFF_V2L);
    uint32_t* s_hp2 = (uint32_t*)(sm + OFF_HP2);
    float*    s_red = (float*)(sm + OFF_RED);

    // ---- stage tables ----
    for (int i = tid; i < DIM; i += 256) s_b1[i] = b1[i];
    if (tid < 256) {
        float2 vv = ((const float2*)Vw)[tid];
        float vh0 = __half2float(__float2half_rn(vv.x));
        float vh1 = __half2float(__float2half_rn(vv.y));
        s_v2h[tid] = pkh2(vh0, vh1);
        s_v2l[tid] = pkh2(vv.x - vh0, vv.y - vh1);
        float2 h0 = ((const float2*)(g_hproj + (size_t)bidx0 * DIM))[tid];
        s_hp2[tid] = pkh2(h0.x, h0.y);
        float2 h1 = make_float2(0.f, 0.f);
        if (bidx0 + 1 < BS)
            h1 = ((const float2*)(g_hproj + (size_t)(bidx0 + 1) * DIM))[tid];
        s_hp2[256 + tid] = pkh2(h1.x, h1.y);
    }

    // ---- convert A slab (64 x 512 fp32 -> fp16) into smem, full K resident ----
    const float4* Av = (const float4*)A;
    for (int i = tid; i < MTILE * 128; i += 256) {
        int r = i >> 7, c4 = i & 127;
        float4 x = Av[(size_t)(m0 + r) * DIM / 4 + c4];
        uint32_t hi, lo = cvt4_f16(x, hi);
        uint2 v; v.x = lo; v.y = hi;
        *(uint2*)(a_f + r * APITCH + c4 * 4) = v;
    }
    __syncthreads();

    // ---- ldmatrix lane addresses ----
    const int a_row = wm * 16 + (lane & 15);
    const int a_k   = (lane >> 4) * 8;
    const uint32_t a_addr = smbase + OFF_A + (uint32_t)(a_row * APITCH + a_k) * 2;

    const int b_n = (lane & 7) + ((lane >> 4) & 1) * 8;
    const int b_k = ((lane >> 3) & 1) * 8;
    const uint32_t bq = (uint32_t)((wn * 32 + b_n) * BPITCH + b_k) * 2;
    uint32_t b_addr[2];
    b_addr[0] = smbase + OFF_B + 0 * BSZ + bq;
    b_addr[1] = smbase + OFF_B + 1 * BSZ + bq;

    // B copy indices (pre-converted fp16 from global, pure 16B copies)
    const int crow = tid >> 2;            // 0..63
    const int cseg = (tid & 3) * 2;       // 0,2,4,6 (uint4 = 8 fp16)
    const uint4* gw1 = (const uint4*)g_w1f;   // row stride 512 fp16 = 64 uint4

    // epilogue row info
    const int g      = lane >> 2;
    const int t      = lane & 3;
    const int r0g    = wm * 16 + g;
    const int rowsel0 = ((m0 + r0g) / SEQ) - bidx0;
    const int rowsel1 = ((m0 + r0g + 8) / SEQ) - bidx0;

    float acc2[4] = {0.f, 0.f, 0.f, 0.f};   // V-dot accumulators

    for (int nb = 0; nb < 8; ++nb) {
        const int n0 = nb * 64;
        const int pbase = ((n0 + wn * 32) >> 1) + t;   // f16x2-pair index base

        // ---- init acc with bias ----
        float acc[4][4];
        {
            const float2* b1v = (const float2*)s_b1;
            #pragma unroll
            for (int f = 0; f < 4; ++f) {
                float2 bb = b1v[pbase + f * 4];
                acc[f][0] = bb.x; acc[f][1] = bb.y;
                acc[f][2] = bb.x; acc[f][3] = bb.y;
            }
        }

        // ---- preload chunk 0 into buf 0 ----
        {
            size_t gi = (size_t)(n0 + crow) * 64 + cseg;
            uint4 h0 = gw1[gi], h1 = gw1[gi + 1];
            uint4* bh = (uint4*)(sm + OFF_B + 0 * BSZ);
            int so = crow * 9 + cseg;
            bh[so] = h0; bh[so + 1] = h1;
            __syncthreads();
        }

        for (int kc = 0; kc < 8; ++kc) {
            const int cur = kc & 1;

            // issue next chunk's global loads early (hidden under MMA)
            uint4 h0, h1;
            if (kc < 7) {
                size_t gi = (size_t)(n0 + crow) * 64 + (kc + 1) * 8 + cseg;
                h0 = gw1[gi]; h1 = gw1[gi + 1];
            }

            #pragma unroll
            for (int ks = 0; ks < 4; ++ks) {
                const uint32_t koff = (uint32_t)(kc * 64 + ks * 16) * 2;
                const uint32_t bko  = (uint32_t)(ks * 16) * 2;
                uint32_t a[4], bh[8];
                ldsm4(a, a_addr + koff);
                ldsm4(bh,     b_addr[cur] + bko);
                ldsm4(bh + 4, b_addr[cur] + 16 * BPITCH * 2 + bko);
                #pragma unroll
                for (int f = 0; f < 4; ++f)
                    mma16816_f16(acc[f], a[0], a[1], a[2], a[3], bh[2*f], bh[2*f+1]);
            }

            if (kc < 7) {
                const int nxt = (kc + 1) & 1;
                uint4* bh = (uint4*)(sm + OFF_B + nxt * BSZ);
                int so = crow * 9 + cseg;
                bh[so] = h0; bh[so + 1] = h1;
            }
            __syncthreads();
        }

        // ---- fused epilogue: relu+hp+tanh in f16x2, V-dot via tensor pipe ----
        uint32_t tf[4][2];
        #pragma unroll
        for (int f = 0; f < 4; ++f) {
            uint32_t hpa = s_hp2[rowsel0 * 256 + pbase + f * 4];
            uint32_t hpb = s_hp2[rowsel1 * 256 + pbase + f * 4];
            uint32_t x0 = cvt_f16x2(acc[f][1], acc[f][0]);   // rows g
            uint32_t x1 = cvt_f16x2(acc[f][3], acc[f][2]);   // rows g+8
            x0 = hadd2(hmax2_0(x0), hpa);
            x1 = hadd2(hmax2_0(x1), hpb);
            tf[f][0] = htanh2(x0);
            tf[f][1] = htanh2(x1);
        }
        #pragma unroll
        for (int F = 0; F < 2; ++F) {
            uint32_t b0h = s_v2h[pbase + F * 8];
            uint32_t b1h = s_v2h[pbase + F * 8 + 4];
            uint32_t b0l = s_v2l[pbase + F * 8];
            uint32_t b1l = s_v2l[pbase + F * 8 + 4];
            mma16816_f16(acc2, tf[2*F][0], tf[2*F][1], tf[2*F+1][0], tf[2*F+1][1], b0h, b1h);
            mma16816_f16(acc2, tf[2*F][0], tf[2*F][1], tf[2*F+1][0], tf[2*F+1][1], b0l, b1l);
        }
    }

    // ---- deterministic final reduction ----
    if (t == 0) {
        s_red[wn * 128 + r0g]     = acc2[0];   // row g
        s_red[wn * 128 + r0g + 8] = acc2[2];   // row g+8
    }
    __syncthreads();
    if (tid < 64)
        g_score[m0 + tid] = s_red[tid] + s_red[128 + tid] + Vb[0];
}

// ===================== hproj kernel: 64x64 tiles, 128 CTAs =====================
__global__ void __launch_bounds__(256) hproj_kernel(
    const float* __restrict__ A,    // hidden [1024,512]
    const float* __restrict__ B,    // W2_w   [512,512]
    const float* __restrict__ bias) // W2_b   [512]
{
    __shared__ float As[16][68];
    __shared__ float Bs[16][68];

    const int tid = threadIdx.x;
    const int tx  = tid & 15;
    const int ty  = tid >> 4;
    const int m0  = blockIdx.x * 64;
    const int n0  = blockIdx.y * 64;

    float acc[4][4];
    #pragma unroll
    for (int i = 0; i < 4; ++i)
        #pragma unroll
        for (int j = 0; j < 4; ++j) acc[i][j] = 0.f;

    const int lrow = tid >> 2, lseg = tid & 3;

    for (int kk = 0; kk < DIM; kk += 16) {
        __syncthreads();
        float4 v = *reinterpret_cast<const float4*>(A + (size_t)(m0 + lrow) * DIM + kk + lseg * 4);
        As[lseg*4+0][lrow] = v.x; As[lseg*4+1][lrow] = v.y;
        As[lseg*4+2][lrow] = v.z; As[lseg*4+3][lrow] = v.w;
        float4 w = *reinterpret_cast<const float4*>(B + (size_t)(n0 + lrow) * DIM + kk + lseg * 4);
        Bs[lseg*4+0][lrow] = w.x; Bs[lseg*4+1][lrow] = w.y;
        Bs[lseg*4+2][lrow] = w.z; Bs[lseg*4+3][lrow] = w.w;
        __syncthreads();
        #pragma unroll
        for (int k = 0; k < 16; ++k) {
            float4 a4 = *reinterpret_cast<const float4*>(&As[k][ty * 4]);
            float4 b4 = *reinterpret_cast<const float4*>(&Bs[k][tx * 4]);
            float a[4] = {a4.x, a4.y, a4.z, a4.w};
            float b[4] = {b4.x, b4.y, b4.z, b4.w};
            #pragma unroll
            for (int i = 0; i < 4; ++i)
                #pragma unroll
                for (int j = 0; j < 4; ++j)
                    acc[i][j] += a[i] * b[j];
        }
    }

    #pragma unroll
    for (int i = 0; i < 4; ++i) {
        int m = m0 + ty * 4 + i;
        #pragma unroll
        for (int j = 0; j < 4; ++j) {
            int n = n0 + tx * 4 + j;
            float v = acc[i][j] + bias[n];
            g_hproj[(size_t)m * DIM + n] = v > 0.f ? v : 0.f;
        }
    }
}

// ===================== softmax + context =====================
__global__ void __launch_bounds__(512) softmax_ctx_kernel(
    const float* __restrict__ features,
    float* __restrict__ out)
{
    __shared__ float w[SEQ];
    __shared__ float red[512];

    const int b   = blockIdx.x;
    const int tid = threadIdx.x;

    float sc = (tid < SEQ) ? g_score[b * SEQ + tid] : -3.4e38f;
    red[tid] = sc;
    __syncthreads();
    #pragma unroll
    for (int off = 256; off > 0; off >>= 1) {
        if (tid < off) red[tid] = fmaxf(red[tid], red[tid + off]);
        __syncthreads();
    }
    float mx = red[0];
    __syncthreads();

    float e = (tid < SEQ) ? expf(sc - mx) : 0.f;
    red[tid] = e;
    __syncthreads();
    #pragma unroll
    for (int off = 256; off > 0; off >>= 1) {
        if (tid < off) red[tid] += red[tid + off];
        __syncthreads();
    }
    float inv = 1.f / red[0];

    float wt = e * inv;
    if (tid < SEQ) {
        w[tid] = wt;
        out[(size_t)BS * DIM + (size_t)b * SEQ + tid] = wt;
    }
    __syncthreads();

    float acc = 0.f;
    const float* fb = features + (size_t)b * SEQ * DIM + tid;
    #pragma unroll 4
    for (int s = 0; s < SEQ; ++s)
        acc += w[s] * fb[(size_t)s * DIM];
    out[(size_t)b * DIM + tid] = acc;
}

// ===================== launch =====================
extern "C" void kernel_launch(void* const* d_in, const int* in_sizes, int n_in,
                              void* d_out, int out_size)
{
    const float* hidden   = (const float*)d_in[0];
    const float* features = (const float*)d_in[1];
    const float* W1_w     = (const float*)d_in[2];
    const float* W1_b     = (const float*)d_in[3];
    const float* W2_w     = (const float*)d_in[4];
    const float* W2_b     = (const float*)d_in[5];
    const float* V_w      = (const float*)d_in[6];
    const float* V_b      = (const float*)d_in[7];
    float* out = (float*)d_out;

    cudaFuncSetAttribute(score_mma_kernel,
                         cudaFuncAttributeMaxDynamicSharedMemorySize, SMEM_BYTES);

    prep_w1_kernel<<<256, 256>>>(W1_w);
    hproj_kernel<<<dim3(16, 8), 256>>>(hidden, W2_w, W2_b);
    score_mma_kernel<<<MTOT / MTILE, 256, SMEM_BYTES>>>(features, W1_b, V_w, V_b);
    softmax_ctx_kernel<<<BS, 512>>>(features, out);
}

// round 6
// speedup vs baseline: 5.4470x; 1.3485x over previous
#include <cuda_runtime.h>
#include <cuda_fp16.h>
#include <math.h>
#include <stdint.h>

#define BS   1024
#define SEQ  360
#define DIM  512
#define MTOT (BS*SEQ)

// ===================== scratch =====================
__device__ float g_hproj[BS * DIM];          // relu(hidden @ W2^T + b2)
__device__ float g_score[BS * SEQ];          // pre-softmax scores
__device__ __half g_w1f[DIM * DIM];          // W1 fp16

// ===================== helpers =====================
__device__ __forceinline__ uint32_t smem_u32(const void* p) {
    uint32_t a;
    asm("{ .reg .u64 t; cvta.to.shared.u64 t, %1; cvt.u32.u64 %0, t; }" : "=r"(a) : "l"(p));
    return a;
}
__device__ __forceinline__ void ldsm4(uint32_t* r, uint32_t addr) {
    asm volatile("ldmatrix.sync.aligned.m8n8.x4.shared.b16 {%0,%1,%2,%3}, [%4];"
                 : "=r"(r[0]), "=r"(r[1]), "=r"(r[2]), "=r"(r[3]) : "r"(addr));
}
__device__ __forceinline__ void mma16816_f16(float* c, uint32_t a0, uint32_t a1,
                                             uint32_t a2, uint32_t a3,
                                             uint32_t b0, uint32_t b1) {
    asm volatile("mma.sync.aligned.m16n8k16.row.col.f32.f16.f16.f32 "
                 "{%0,%1,%2,%3}, {%4,%5,%6,%7}, {%8,%9}, {%0,%1,%2,%3};"
                 : "+f"(c[0]), "+f"(c[1]), "+f"(c[2]), "+f"(c[3])
                 : "r"(a0), "r"(a1), "r"(a2), "r"(a3), "r"(b0), "r"(b1));
}
#define CPA16(smaddr, gptr) \
    asm volatile("cp.async.cg.shared.global [%0], [%1], 16;" :: "r"(smaddr), "l"(gptr))
#define CPA_COMMIT() asm volatile("cp.async.commit_group;" ::: "memory")
#define CPA_WAIT0()  asm volatile("cp.async.wait_group 0;" ::: "memory")

__device__ __forceinline__ uint32_t cvt_f16x2(float hi, float lo) {
    uint32_t d; asm("cvt.rn.f16x2.f32 %0, %1, %2;" : "=r"(d) : "f"(hi), "f"(lo)); return d;
}
__device__ __forceinline__ uint32_t hmax2_0(uint32_t x) {
    uint32_t d; asm("max.f16x2 %0, %1, %2;" : "=r"(d) : "r"(x), "r"(0u)); return d;
}
__device__ __forceinline__ uint32_t hadd2(uint32_t a, uint32_t b) {
    uint32_t d; asm("add.f16x2 %0, %1, %2;" : "=r"(d) : "r"(a), "r"(b)); return d;
}
__device__ __forceinline__ uint32_t htanh2(uint32_t x) {
    uint32_t d; asm("tanh.approx.f16x2 %0, %1;" : "=r"(d) : "r"(x)); return d;
}
__device__ __forceinline__ uint32_t pkh2(float lo, float hi) {
    __half2 h = __floats2half2_rn(lo, hi);   // .x = lo
    return *(uint32_t*)&h;
}
__device__ __forceinline__ uint32_t cvt4_f16(float4 x, uint32_t& hi2) {
    hi2 = pkh2(x.z, x.w);
    return pkh2(x.x, x.y);
}

// ===================== prep: W1 -> fp16 (once) =====================
__global__ void __launch_bounds__(256) prep_w1_kernel(const float* __restrict__ W1) {
    int i = blockIdx.x * 256 + threadIdx.x;        // 65536 float4s
    float4 x = ((const float4*)W1)[i];
    uint32_t hi, lo = cvt4_f16(x, hi);
    uint2 v; v.x = lo; v.y = hi;
    *(uint2*)(g_w1f + (size_t)i * 4) = v;
}

// ===================== score kernel =====================
// CTA: 64 rows x 512 units. Warps: wm in {0,1} (m32), wn in {0..3} (n64).
// nb in {0,1}: n-tile 256. K streamed in 16 chunks of 32 via cp.async double buffer.
#define MTILE  64
#define APITCH 520                 // fp16; 1040B row, mod 128 = 16 -> conflict-free
#define BPITCH 40                  // fp16; 80B row, 16B-aligned, conflict-free
#define BBUF   (256*BPITCH*2)      // 20480 B per buffer

#define OFF_A   0                              // 66560
#define OFF_B   (MTILE*APITCH*2)               // 66560 ; 2 bufs
#define OFF_BB2 (OFF_B + 2*BBUF)               // 107520 (256 u32 bias f16x2)
#define OFF_V2H (OFF_BB2 + 1024)               // 108544
#define OFF_V2L (OFF_V2H + 1024)               // 109568
#define OFF_HP2 (OFF_V2L + 1024)               // 110592 (2 x 256 u32)
#define OFF_RED OFF_B                          // aliased over B buffers (dead at epilogue end)
#define SMEM_BYTES (OFF_HP2 + 2048)            // 112640

__global__ void __launch_bounds__(256, 2)
score_mma_kernel(const float* __restrict__ A,   // features [368640, 512]
                 const float* __restrict__ b1,  // [512]
                 const float* __restrict__ Vw,  // [512]
                 const float* __restrict__ Vb)  // [1]
{
    extern __shared__ char sm[];
    const uint32_t smbase = smem_u32(sm);

    const int tid  = threadIdx.x;
    const int lane = tid & 31;
    const int wid  = tid >> 5;
    const int wm   = wid & 1;       // m32 subtile
    const int wn   = wid >> 1;      // n64 subtile within 256-wide nb tile
    const int m0   = blockIdx.x * MTILE;
    const int bidx0 = m0 / SEQ;

    __half*   a_f   = (__half*)(sm + OFF_A);
    uint32_t* s_bb2 = (uint32_t*)(sm + OFF_BB2);
    uint32_t* s_v2h = (uint32_t*)(sm + OFF_V2H);
    uint32_t* s_v2l = (uint32_t*)(sm + OFF_V2L);
    uint32_t* s_hp2 = (uint32_t*)(sm + OFF_HP2);

    // ---- stage tables (f16x2 packed) ----
    if (tid < 256) {
        float2 bb = ((const float2*)b1)[tid];
        s_bb2[tid] = pkh2(bb.x, bb.y);
        float2 vv = ((const float2*)Vw)[tid];
        float vh0 = __half2float(__float2half_rn(vv.x));
        float vh1 = __half2float(__float2half_rn(vv.y));
        s_v2h[tid] = pkh2(vh0, vh1);
        s_v2l[tid] = pkh2(vv.x - vh0, vv.y - vh1);
        float2 h0 = ((const float2*)(g_hproj + (size_t)bidx0 * DIM))[tid];
        s_hp2[tid] = pkh2(h0.x, h0.y);
        float2 h1 = make_float2(0.f, 0.f);
        if (bidx0 + 1 < BS)
            h1 = ((const float2*)(g_hproj + (size_t)(bidx0 + 1) * DIM))[tid];
        s_hp2[256 + tid] = pkh2(h1.x, h1.y);
    }

    // ---- convert A slab (64 x 512 fp32 -> fp16) into smem, full K resident ----
    const float4* Av = (const float4*)A;
    for (int i = tid; i < MTILE * 128; i += 256) {
        int r = i >> 7, c4 = i & 127;
        float4 x = Av[(size_t)(m0 + r) * (DIM / 4) + c4];
        uint32_t hi, lo = cvt4_f16(x, hi);
        uint2 v; v.x = lo; v.y = hi;
        *(uint2*)(a_f + r * APITCH + c4 * 4) = v;
    }
    __syncthreads();

    // ---- ldmatrix lane addresses ----
    const uint32_t a_addr0 = smbase + OFF_A +
        (uint32_t)((wm * 32 + (lane & 15)) * APITCH + (lane >> 4) * 8) * 2;
    const uint32_t a_addr1 = a_addr0 + 16 * APITCH * 2;

    const int b_n = (lane & 7) + ((lane >> 4) & 1) * 8;
    const int b_k = ((lane >> 3) & 1) * 8;
    const uint32_t bq = (uint32_t)((wn * 64 + b_n) * BPITCH + b_k) * 2;
    uint32_t b_addr[2];
    b_addr[0] = smbase + OFF_B + bq;
    b_addr[1] = b_addr[0] + BBUF;

    // ---- B cp.async indices: thread handles rows r0 and r0+128, 32B each ----
    const int r0 = tid >> 1;
    const int jj = (tid & 1) * 2;                 // uint4 pair offset within 4
    const uint4* gw1 = (const uint4*)g_w1f;       // row = 64 uint4

    // ---- epilogue row info ----
    const int g = lane >> 2;
    const int t = lane & 3;
    int rowsel[2][2];
    #pragma unroll
    for (int sub = 0; sub < 2; ++sub) {
        int rl = wm * 32 + sub * 16 + g;
        rowsel[sub][0] = ((m0 + rl) / SEQ) - bidx0;
        rowsel[sub][1] = ((m0 + rl + 8) / SEQ) - bidx0;
    }

    float acc2[2][4] = {{0.f,0.f,0.f,0.f},{0.f,0.f,0.f,0.f}};

    for (int nb = 0; nb < 2; ++nb) {
        const int n0 = nb * 256;
        const int pb = nb * 128 + wn * 32 + t;    // f16x2 pair base for this warp

        float acc[2][8][4];
        #pragma unroll
        for (int sub = 0; sub < 2; ++sub)
            #pragma unroll
            for (int f = 0; f < 8; ++f)
                #pragma unroll
                for (int e = 0; e < 4; ++e) acc[sub][f][e] = 0.f;

        // ---- preload chunk 0 into buf 0 ----
        {
            uint32_t s0 = smbase + OFF_B + (uint32_t)(r0 * BPITCH + jj * 8) * 2;
            const uint4* gp0 = gw1 + (size_t)(n0 + r0) * 64 + jj;
            CPA16(s0, gp0); CPA16(s0 + 16, gp0 + 1);
            uint32_t s1 = smbase + OFF_B + (uint32_t)((r0 + 128) * BPITCH + jj * 8) * 2;
            const uint4* gp1 = gw1 + (size_t)(n0 + r0 + 128) * 64 + jj;
            CPA16(s1, gp1); CPA16(s1 + 16, gp1 + 1);
            CPA_COMMIT();
            CPA_WAIT0();
            __syncthreads();
        }

        for (int kc = 0; kc < 16; ++kc) {
            const int cur = kc & 1;

            // prefetch next chunk into other buffer via cp.async
            if (kc < 15) {
                uint32_t dst = smbase + OFF_B + (uint32_t)(1 - cur) * BBUF;
                uint32_t s0 = dst + (uint32_t)(r0 * BPITCH + jj * 8) * 2;
                const uint4* gp0 = gw1 + (size_t)(n0 + r0) * 64 + (kc + 1) * 4 + jj;
                CPA16(s0, gp0); CPA16(s0 + 16, gp0 + 1);
                uint32_t s1 = dst + (uint32_t)((r0 + 128) * BPITCH + jj * 8) * 2;
                const uint4* gp1 = gw1 + (size_t)(n0 + r0 + 128) * 64 + (kc + 1) * 4 + jj;
                CPA16(s1, gp1); CPA16(s1 + 16, gp1 + 1);
                CPA_COMMIT();
            }

            #pragma unroll
            for (int ks = 0; ks < 2; ++ks) {
                const uint32_t koffA = (uint32_t)(kc * 32 + ks * 16) * 2;
                const uint32_t koffB = (uint32_t)(ks * 16) * 2;
                uint32_t a[8];
                ldsm4(a,     a_addr0 + koffA);
                ldsm4(a + 4, a_addr1 + koffA);
                #pragma unroll
                for (int half = 0; half < 2; ++half) {
                    const uint32_t hb = (uint32_t)(half * 32 * BPITCH) * 2;
                    uint32_t bf[8];
                    ldsm4(bf,     b_addr[cur] + hb + koffB);
                    ldsm4(bf + 4, b_addr[cur] + hb + 16 * BPITCH * 2 + koffB);
                    #pragma unroll
                    for (int f2 = 0; f2 < 4; ++f2) {
                        const int f = half * 4 + f2;
                        mma16816_f16(acc[0][f], a[0], a[1], a[2], a[3], bf[2*f2], bf[2*f2+1]);
                        mma16816_f16(acc[1][f], a[4], a[5], a[6], a[7], bf[2*f2], bf[2*f2+1]);
                    }
                }
            }

            if (kc < 15) CPA_WAIT0();
            __syncthreads();
        }

        // ---- fused epilogue: bias+relu+hp+tanh in f16x2, V-dot via tensor pipe ----
        #pragma unroll
        for (int sub = 0; sub < 2; ++sub) {
            #pragma unroll
            for (int F = 0; F < 4; ++F) {
                uint32_t tf[2][2];
                #pragma unroll
                for (int j = 0; j < 2; ++j) {
                    const int f = 2 * F + j;
                    uint32_t bb  = s_bb2[pb + f * 4];
                    uint32_t hpa = s_hp2[rowsel[sub][0] * 256 + pb + f * 4];
                    uint32_t hpb = s_hp2[rowsel[sub][1] * 256 + pb + f * 4];
                    uint32_t x0 = cvt_f16x2(acc[sub][f][1], acc[sub][f][0]);
                    uint32_t x1 = cvt_f16x2(acc[sub][f][3], acc[sub][f][2]);
                    x0 = hadd2(hmax2_0(hadd2(x0, bb)), hpa);
                    x1 = hadd2(hmax2_0(hadd2(x1, bb)), hpb);
                    tf[j][0] = htanh2(x0);
                    tf[j][1] = htanh2(x1);
                }
                uint32_t b0h = s_v2h[pb + F * 8];
                uint32_t b1h = s_v2h[pb + F * 8 + 4];
                uint32_t b0l = s_v2l[pb + F * 8];
                uint32_t b1l = s_v2l[pb + F * 8 + 4];
                mma16816_f16(acc2[sub], tf[0][0], tf[0][1], tf[1][0], tf[1][1], b0h, b1h);
                mma16816_f16(acc2[sub], tf[0][0], tf[0][1], tf[1][0], tf[1][1], b0l, b1l);
            }
        }
    }

    // ---- deterministic final reduction (s_red aliased over B buffers) ----
    float* s_red = (float*)(sm + OFF_RED);
    __syncthreads();   // B buffers fully dead
    if (t == 0) {
        #pragma unroll
        for (int sub = 0; sub < 2; ++sub) {
            int rl = wm * 32 + sub * 16 + g;
            s_red[wn * 64 + rl]     = acc2[sub][0];   // row rl
            s_red[wn * 64 + rl + 8] = acc2[sub][2];   // row rl+8
        }
    }
    __syncthreads();
    if (tid < 64)
        g_score[m0 + tid] = ((s_red[tid] + s_red[64 + tid]) +
                             (s_red[128 + tid] + s_red[192 + tid])) + Vb[0];
}

// ===================== hproj kernel: 64x64 tiles, 128 CTAs =====================
__global__ void __launch_bounds__(256) hproj_kernel(
    const float* __restrict__ A,    // hidden [1024,512]
    const float* __restrict__ B,    // W2_w   [512,512]
    const float* __restrict__ bias) // W2_b   [512]
{
    __shared__ float As[16][68];
    __shared__ float Bs[16][68];

    const int tid = threadIdx.x;
    const int tx  = tid & 15;
    const int ty  = tid >> 4;
    const int m0  = blockIdx.x * 64;
    const int n0  = blockIdx.y * 64;

    float acc[4][4];
    #pragma unroll
    for (int i = 0; i < 4; ++i)
        #pragma unroll
        for (int j = 0; j < 4; ++j) acc[i][j] = 0.f;

    const int lrow = tid >> 2, lseg = tid & 3;

    for (int kk = 0; kk < DIM; kk += 16) {
        __syncthreads();
        float4 v = *reinterpret_cast<const float4*>(A + (size_t)(m0 + lrow) * DIM + kk + lseg * 4);
        As[lseg*4+0][lrow] = v.x; As[lseg*4+1][lrow] = v.y;
        As[lseg*4+2][lrow] = v.z; As[lseg*4+3][lrow] = v.w;
        float4 w = *reinterpret_cast<const float4*>(B + (size_t)(n0 + lrow) * DIM + kk + lseg * 4);
        Bs[lseg*4+0][lrow] = w.x; Bs[lseg*4+1][lrow] = w.y;
        Bs[lseg*4+2][lrow] = w.z; Bs[lseg*4+3][lrow] = w.w;
        __syncthreads();
        #pragma unroll
        for (int k = 0; k < 16; ++k) {
            float4 a4 = *reinterpret_cast<const float4*>(&As[k][ty * 4]);
            float4 b4 = *reinterpret_cast<const float4*>(&Bs[k][tx * 4]);
            float a[4] = {a4.x, a4.y, a4.z, a4.w};
            float b[4] = {b4.x, b4.y, b4.z, b4.w};
            #pragma unroll
            for (int i = 0; i < 4; ++i)
                #pragma unroll
                for (int j = 0; j < 4; ++j)
                    acc[i][j] += a[i] * b[j];
        }
    }

    #pragma unroll
    for (int i = 0; i < 4; ++i) {
        int m = m0 + ty * 4 + i;
        #pragma unroll
        for (int j = 0; j < 4; ++j) {
            int n = n0 + tx * 4 + j;
            float v = acc[i][j] + bias[n];
            g_hproj[(size_t)m * DIM + n] = v > 0.f ? v : 0.f;
        }
    }
}

// ===================== softmax + context (float4, 4-way s-split) =====================
__global__ void __launch_bounds__(512) softmax_ctx_kernel(
    const float* __restrict__ features,
    float* __restrict__ out)
{
    __shared__ float w[SEQ];
    __shared__ float red[512];
    __shared__ float part[4][512];

    const int b   = blockIdx.x;
    const int tid = threadIdx.x;

    float sc = (tid < SEQ) ? g_score[b * SEQ + tid] : -3.4e38f;
    red[tid] = sc;
    __syncthreads();
    #pragma unroll
    for (int off = 256; off > 0; off >>= 1) {
        if (tid < off) red[tid] = fmaxf(red[tid], red[tid + off]);
        __syncthreads();
    }
    float mx = red[0];
    __syncthreads();

    float e = (tid < SEQ) ? expf(sc - mx) : 0.f;
    red[tid] = e;
    __syncthreads();
    #pragma unroll
    for (int off = 256; off > 0; off >>= 1) {
        if (tid < off) red[tid] += red[tid + off];
        __syncthreads();
    }
    float inv = 1.f / red[0];

    float wt = e * inv;
    if (tid < SEQ) {
        w[tid] = wt;
        out[(size_t)BS * DIM + (size_t)b * SEQ + tid] = wt;
    }
    __syncthreads();

    // context: 4 s-groups x 128 threads, each thread owns 4 consecutive e (float4)
    const int sg = tid >> 7;            // 0..3
    const int e4 = tid & 127;           // float4 index
    const float4* fb = (const float4*)(features + (size_t)b * SEQ * DIM);
    float4 acc = make_float4(0.f, 0.f, 0.f, 0.f);
    const int sBeg = sg * 90, sEnd = sBeg + 90;
    #pragma unroll 5
    for (int s = sBeg; s < sEnd; ++s) {
        float ws = w[s];
        float4 v = fb[(size_t)s * 128 + e4];
        acc.x += ws * v.x; acc.y += ws * v.y;
        acc.z += ws * v.z; acc.w += ws * v.w;
    }
    ((float4*)part[sg])[e4] = acc;
    __syncthreads();

    float r = (part[0][tid] + part[1][tid]) + (part[2][tid] + part[3][tid]);
    out[(size_t)b * DIM + tid] = r;
}

// ===================== launch =====================
extern "C" void kernel_launch(void* const* d_in, const int* in_sizes, int n_in,
                              void* d_out, int out_size)
{
    const float* hidden   = (const float*)d_in[0];
    const float* features = (const float*)d_in[1];
    const float* W1_w     = (const float*)d_in[2];
    const float* W1_b     = (const float*)d_in[3];
    const float* W2_w     = (const float*)d_in[4];
    const float* W2_b     = (const float*)d_in[5];
    const float* V_w      = (const float*)d_in[6];
    const float* V_b      = (const float*)d_in[7];
    float* out = (float*)d_out;

    cudaFuncSetAttribute(score_mma_kernel,
                         cudaFuncAttributeMaxDynamicSharedMemorySize, SMEM_BYTES);

    prep_w1_kernel<<<256, 256>>>(W1_w);
    hproj_kernel<<<dim3(16, 8), 256>>>(hidden, W2_w, W2_b);
    score_mma_kernel<<<MTOT / MTILE, 256, SMEM_BYTES>>>(features, W1_b, V_w, V_b);
    softmax_ctx_kernel<<<BS, 512>>>(features, out);
}

// round 7
// speedup vs baseline: 5.7768x; 1.0606x over previous
#include <cuda_runtime.h>
#include <cuda_fp16.h>
#include <math.h>
#include <stdint.h>

#define BS   1024
#define SEQ  360
#define DIM  512
#define MTOT (BS*SEQ)

// ===================== scratch =====================
__device__ float g_hproj[BS * DIM];          // relu(hidden @ W2^T + b2)
__device__ float g_score[BS * SEQ];          // pre-softmax scores
__device__ __half g_w1f[DIM * DIM];          // W1 fp16

// ===================== helpers =====================
__device__ __forceinline__ uint32_t smem_u32(const void* p) {
    uint32_t a;
    asm("{ .reg .u64 t; cvta.to.shared.u64 t, %1; cvt.u32.u64 %0, t; }" : "=r"(a) : "l"(p));
    return a;
}
__device__ __forceinline__ void ldsm4(uint32_t* r, uint32_t addr) {
    asm volatile("ldmatrix.sync.aligned.m8n8.x4.shared.b16 {%0,%1,%2,%3}, [%4];"
                 : "=r"(r[0]), "=r"(r[1]), "=r"(r[2]), "=r"(r[3]) : "r"(addr));
}
__device__ __forceinline__ void mma16816_f16(float* c, uint32_t a0, uint32_t a1,
                                             uint32_t a2, uint32_t a3,
                                             uint32_t b0, uint32_t b1) {
    asm volatile("mma.sync.aligned.m16n8k16.row.col.f32.f16.f16.f32 "
                 "{%0,%1,%2,%3}, {%4,%5,%6,%7}, {%8,%9}, {%0,%1,%2,%3};"
                 : "+f"(c[0]), "+f"(c[1]), "+f"(c[2]), "+f"(c[3])
                 : "r"(a0), "r"(a1), "r"(a2), "r"(a3), "r"(b0), "r"(b1));
}
#define CPA16(smaddr, gptr) \
    asm volatile("cp.async.cg.shared.global [%0], [%1], 16;" :: "r"(smaddr), "l"(gptr))
#define CPA_COMMIT() asm volatile("cp.async.commit_group;" ::: "memory")
#define CPA_WAIT1()  asm volatile("cp.async.wait_group 1;" ::: "memory")

__device__ __forceinline__ uint32_t cvt_f16x2(float hi, float lo) {
    uint32_t d; asm("cvt.rn.f16x2.f32 %0, %1, %2;" : "=r"(d) : "f"(hi), "f"(lo)); return d;
}
__device__ __forceinline__ uint32_t hmax2_0(uint32_t x) {
    uint32_t d; asm("max.f16x2 %0, %1, %2;" : "=r"(d) : "r"(x), "r"(0u)); return d;
}
__device__ __forceinline__ uint32_t hadd2(uint32_t a, uint32_t b) {
    uint32_t d; asm("add.f16x2 %0, %1, %2;" : "=r"(d) : "r"(a), "r"(b)); return d;
}
__device__ __forceinline__ uint32_t htanh2(uint32_t x) {
    uint32_t d; asm("tanh.approx.f16x2 %0, %1;" : "=r"(d) : "r"(x)); return d;
}
__device__ __forceinline__ uint32_t pkh2(float lo, float hi) {
    __half2 h = __floats2half2_rn(lo, hi);   // .x = lo
    return *(uint32_t*)&h;
}
__device__ __forceinline__ uint32_t cvt4_f16(float4 x, uint32_t& hi2) {
    hi2 = pkh2(x.z, x.w);
    return pkh2(x.x, x.y);
}

// ===================== prep: W1 -> fp16 (once) =====================
__global__ void __launch_bounds__(256) prep_w1_kernel(const float* __restrict__ W1) {
    int i = blockIdx.x * 256 + threadIdx.x;        // 65536 float4s
    float4 x = ((const float4*)W1)[i];
    uint32_t hi, lo = cvt4_f16(x, hi);
    uint2 v; v.x = lo; v.y = hi;
    *(uint2*)(g_w1f + (size_t)i * 4) = v;
}

// ===================== score kernel =====================
// CTA: 128 rows x 512 units, 512 threads (16 warps: 4m x 4n), 1 CTA/SM.
// nb in {0,1}: n-tile 256. K streamed in 16 chunks of 32 via 3-buffer cp.async ring.
#define MTILE  128
#define APITCH 520                 // fp16; 1040B row, mod 128 = 16 -> conflict-free
#define BPITCH 40                  // fp16; 80B row, stride 5x16B mod 16 -> conflict-free
#define BBUF   (256*BPITCH*2)      // 20480 B per buffer

#define OFF_A   0                              // 133120 bytes
#define OFF_B   (MTILE*APITCH*2)               // 133120 ; 3 bufs
#define OFF_BB2 (OFF_B + 3*BBUF)               // 194560 (256 u32 bias f16x2)
#define OFF_V2H (OFF_BB2 + 1024)               // 195584
#define OFF_V2L (OFF_V2H + 1024)               // 196608
#define OFF_HP2 (OFF_V2L + 1024)               // 197632 (2 x 256 u32)
#define OFF_RED OFF_B                          // aliased over B buffers (dead at final reduce)
#define SMEM_BYTES (OFF_HP2 + 2048)            // 199680

__global__ void __launch_bounds__(512, 1)
score_mma_kernel(const float* __restrict__ A,   // features [368640, 512]
                 const float* __restrict__ b1,  // [512]
                 const float* __restrict__ Vw,  // [512]
                 const float* __restrict__ Vb)  // [1]
{
    extern __shared__ char sm[];
    const uint32_t smbase = smem_u32(sm);

    const int tid  = threadIdx.x;
    const int lane = tid & 31;
    const int wid  = tid >> 5;
    const int wm   = wid & 3;       // 4 m-subtiles of 32
    const int wn   = wid >> 2;      // 4 n64 subtiles within 256-wide nb tile
    const int m0   = blockIdx.x * MTILE;
    const int bidx0 = m0 / SEQ;

    __half*   a_f   = (__half*)(sm + OFF_A);
    uint32_t* s_bb2 = (uint32_t*)(sm + OFF_BB2);
    uint32_t* s_v2h = (uint32_t*)(sm + OFF_V2H);
    uint32_t* s_v2l = (uint32_t*)(sm + OFF_V2L);
    uint32_t* s_hp2 = (uint32_t*)(sm + OFF_HP2);

    // ---- stage tables (f16x2 packed) ----
    if (tid < 256) {
        float2 bb = ((const float2*)b1)[tid];
        s_bb2[tid] = pkh2(bb.x, bb.y);
        float2 vv = ((const float2*)Vw)[tid];
        float vh0 = __half2float(__float2half_rn(vv.x));
        float vh1 = __half2float(__float2half_rn(vv.y));
        s_v2h[tid] = pkh2(vh0, vh1);
        s_v2l[tid] = pkh2(vv.x - vh0, vv.y - vh1);
        float2 h0 = ((const float2*)(g_hproj + (size_t)bidx0 * DIM))[tid];
        s_hp2[tid] = pkh2(h0.x, h0.y);
        float2 h1 = make_float2(0.f, 0.f);
        if (bidx0 + 1 < BS)
            h1 = ((const float2*)(g_hproj + (size_t)(bidx0 + 1) * DIM))[tid];
        s_hp2[256 + tid] = pkh2(h1.x, h1.y);
    }

    // ---- convert A slab (128 x 512 fp32 -> fp16) into smem, full K resident ----
    const float4* Av = (const float4*)A;
    for (int i = tid; i < MTILE * 128; i += 512) {
        int r = i >> 7, c4 = i & 127;
        float4 x = Av[(size_t)(m0 + r) * (DIM / 4) + c4];
        uint32_t hi, lo = cvt4_f16(x, hi);
        uint2 v; v.x = lo; v.y = hi;
        *(uint2*)(a_f + r * APITCH + c4 * 4) = v;
    }
    __syncthreads();

    // ---- ldmatrix lane addresses ----
    const uint32_t a_addr0 = smbase + OFF_A +
        (uint32_t)((wm * 32 + (lane & 15)) * APITCH + (lane >> 4) * 8) * 2;
    const uint32_t a_addr1 = a_addr0 + 16 * APITCH * 2;

    const int b_n = (lane & 7) + ((lane >> 4) & 1) * 8;
    const int b_k = ((lane >> 3) & 1) * 8;
    const uint32_t bq = (uint32_t)((wn * 64 + b_n) * BPITCH + b_k) * 2;
    uint32_t b_addr[3];
    b_addr[0] = smbase + OFF_B + bq;
    b_addr[1] = b_addr[0] + BBUF;
    b_addr[2] = b_addr[1] + BBUF;

    // ---- B cp.async indices: 512 threads, 2 threads per row, 32B each ----
    const int r0 = tid >> 1;                      // 0..255
    const int jj = (tid & 1) * 2;                 // uint4 pair within row
    const uint4* gw1 = (const uint4*)g_w1f;       // row = 64 uint4
    const uint32_t bst = (uint32_t)(r0 * BPITCH + jj * 8) * 2;   // smem offset within buffer

    // ---- epilogue row info ----
    const int g = lane >> 2;
    const int t = lane & 3;
    int rowsel[2][2];
    #pragma unroll
    for (int sub = 0; sub < 2; ++sub) {
        int rl = wm * 32 + sub * 16 + g;
        rowsel[sub][0] = ((m0 + rl) / SEQ) - bidx0;
        rowsel[sub][1] = ((m0 + rl + 8) / SEQ) - bidx0;
    }

    float acc2[2][4] = {{0.f,0.f,0.f,0.f},{0.f,0.f,0.f,0.f}};

    for (int nb = 0; nb < 2; ++nb) {
        const int n0 = nb * 256;
        const int pb = nb * 128 + wn * 32 + t;    // f16x2 pair base for this warp

        float acc[2][8][4];
        #pragma unroll
        for (int sub = 0; sub < 2; ++sub)
            #pragma unroll
            for (int f = 0; f < 8; ++f)
                #pragma unroll
                for (int e = 0; e < 4; ++e) acc[sub][f][e] = 0.f;

        if (nb > 0) __syncthreads();   // protect buf reuse across nb

        // ---- preload chunks 0,1 into bufs 0,1 (separate groups) ----
        {
            const uint4* gp = gw1 + (size_t)(n0 + r0) * 64 + jj;
            uint32_t s0 = smbase + OFF_B + bst;
            CPA16(s0, gp); CPA16(s0 + 16, gp + 1);
            CPA_COMMIT();
            const uint4* gq = gw1 + (size_t)(n0 + r0) * 64 + 4 + jj;
            uint32_t s1 = smbase + OFF_B + BBUF + bst;
            CPA16(s1, gq); CPA16(s1 + 16, gq + 1);
            CPA_COMMIT();
        }

        for (int kc = 0; kc < 16; ++kc) {
            const int cur = kc % 3;

            CPA_WAIT1();          // chunk kc complete (<=1 pending: kc+1)
            __syncthreads();      // its smem writes visible to all warps

            // prefetch chunk kc+2 into buf (kc+2)%3 (always commit for accounting)
            if (kc <= 13) {
                uint32_t dst = smbase + OFF_B + (uint32_t)((kc + 2) % 3) * BBUF + bst;
                const uint4* gp = gw1 + (size_t)(n0 + r0) * 64 + (kc + 2) * 4 + jj;
                CPA16(dst, gp); CPA16(dst + 16, gp + 1);
            }
            CPA_COMMIT();

            #pragma unroll
            for (int ks = 0; ks < 2; ++ks) {
                const uint32_t koffA = (uint32_t)(kc * 32 + ks * 16) * 2;
                const uint32_t koffB = (uint32_t)(ks * 16) * 2;
                uint32_t a[8];
                ldsm4(a,     a_addr0 + koffA);
                ldsm4(a + 4, a_addr1 + koffA);
                #pragma unroll
                for (int half = 0; half < 2; ++half) {
                    const uint32_t hb = (uint32_t)(half * 32 * BPITCH) * 2;
                    uint32_t bf[8];
                    ldsm4(bf,     b_addr[cur] + hb + koffB);
                    ldsm4(bf + 4, b_addr[cur] + hb + 16 * BPITCH * 2 + koffB);
                    #pragma unroll
                    for (int f2 = 0; f2 < 4; ++f2) {
                        const int f = half * 4 + f2;
                        mma16816_f16(acc[0][f], a[0], a[1], a[2], a[3], bf[2*f2], bf[2*f2+1]);
                        mma16816_f16(acc[1][f], a[4], a[5], a[6], a[7], bf[2*f2], bf[2*f2+1]);
                    }
                }
            }
        }

        // ---- fused epilogue: bias+relu+hp+tanh in f16x2, V-dot via tensor pipe ----
        #pragma unroll
        for (int sub = 0; sub < 2; ++sub) {
            #pragma unroll
            for (int F = 0; F < 4; ++F) {
                uint32_t tf[2][2];
                #pragma unroll
                for (int j = 0; j < 2; ++j) {
                    const int f = 2 * F + j;
                    uint32_t bb  = s_bb2[pb + f * 4];
                    uint32_t hpa = s_hp2[rowsel[sub][0] * 256 + pb + f * 4];
                    uint32_t hpb = s_hp2[rowsel[sub][1] * 256 + pb + f * 4];
                    uint32_t x0 = cvt_f16x2(acc[sub][f][1], acc[sub][f][0]);
                    uint32_t x1 = cvt_f16x2(acc[sub][f][3], acc[sub][f][2]);
                    x0 = hadd2(hmax2_0(hadd2(x0, bb)), hpa);
                    x1 = hadd2(hmax2_0(hadd2(x1, bb)), hpb);
                    tf[j][0] = htanh2(x0);
                    tf[j][1] = htanh2(x1);
                }
                uint32_t b0h = s_v2h[pb + F * 8];
                uint32_t b1h = s_v2h[pb + F * 8 + 4];
                uint32_t b0l = s_v2l[pb + F * 8];
                uint32_t b1l = s_v2l[pb + F * 8 + 4];
                mma16816_f16(acc2[sub], tf[0][0], tf[0][1], tf[1][0], tf[1][1], b0h, b1h);
                mma16816_f16(acc2[sub], tf[0][0], tf[0][1], tf[1][0], tf[1][1], b0l, b1l);
            }
        }
    }

    // ---- deterministic final reduction (s_red aliased over B buffers) ----
    float* s_red = (float*)(sm + OFF_RED);
    __syncthreads();   // B buffers fully dead
    if (t == 0) {
        #pragma unroll
        for (int sub = 0; sub < 2; ++sub) {
            int rl = wm * 32 + sub * 16 + g;
            s_red[wn * 128 + rl]     = acc2[sub][0];   // row rl
            s_red[wn * 128 + rl + 8] = acc2[sub][2];   // row rl+8
        }
    }
    __syncthreads();
    if (tid < 128)
        g_score[m0 + tid] = ((s_red[tid] + s_red[128 + tid]) +
                             (s_red[256 + tid] + s_red[384 + tid])) + Vb[0];
}

// ===================== hproj kernel: 64x64 tiles, 128 CTAs =====================
__global__ void __launch_bounds__(256) hproj_kernel(
    const float* __restrict__ A,    // hidden [1024,512]
    const float* __restrict__ B,    // W2_w   [512,512]
    const float* __restrict__ bias) // W2_b   [512]
{
    __shared__ float As[16][68];
    __shared__ float Bs[16][68];

    const int tid = threadIdx.x;
    const int tx  = tid & 15;
    const int ty  = tid >> 4;
    const int m0  = blockIdx.x * 64;
    const int n0  = blockIdx.y * 64;

    float acc[4][4];
    #pragma unroll
    for (int i = 0; i < 4; ++i)
        #pragma unroll
        for (int j = 0; j < 4; ++j) acc[i][j] = 0.f;

    const int lrow = tid >> 2, lseg = tid & 3;

    for (int kk = 0; kk < DIM; kk += 16) {
        __syncthreads();
        float4 v = *reinterpret_cast<const float4*>(A + (size_t)(m0 + lrow) * DIM + kk + lseg * 4);
        As[lseg*4+0][lrow] = v.x; As[lseg*4+1][lrow] = v.y;
        As[lseg*4+2][lrow] = v.z; As[lseg*4+3][lrow] = v.w;
        float4 w = *reinterpret_cast<const float4*>(B + (size_t)(n0 + lrow) * DIM + kk + lseg * 4);
        Bs[lseg*4+0][lrow] = w.x; Bs[lseg*4+1][lrow] = w.y;
        Bs[lseg*4+2][lrow] = w.z; Bs[lseg*4+3][lrow] = w.w;
        __syncthreads();
        #pragma unroll
        for (int k = 0; k < 16; ++k) {
            float4 a4 = *reinterpret_cast<const float4*>(&As[k][ty * 4]);
            float4 b4 = *reinterpret_cast<const float4*>(&Bs[k][tx * 4]);
            float a[4] = {a4.x, a4.y, a4.z, a4.w};
            float b[4] = {b4.x, b4.y, b4.z, b4.w};
            #pragma unroll
            for (int i = 0; i < 4; ++i)
                #pragma unroll
                for (int j = 0; j < 4; ++j)
                    acc[i][j] += a[i] * b[j];
        }
    }

    #pragma unroll
    for (int i = 0; i < 4; ++i) {
        int m = m0 + ty * 4 + i;
        #pragma unroll
        for (int j = 0; j < 4; ++j) {
            int n = n0 + tx * 4 + j;
            float v = acc[i][j] + bias[n];
            g_hproj[(size_t)m * DIM + n] = v > 0.f ? v : 0.f;
        }
    }
}

// ===================== softmax + context (float4, 4-way s-split) =====================
__global__ void __launch_bounds__(512) softmax_ctx_kernel(
    const float* __restrict__ features,
    float* __restrict__ out)
{
    __shared__ float w[SEQ];
    __shared__ float red[512];
    __shared__ float part[4][512];

    const int b   = blockIdx.x;
    const int tid = threadIdx.x;

    float sc = (tid < SEQ) ? g_score[b * SEQ + tid] : -3.4e38f;
    red[tid] = sc;
    __syncthreads();
    #pragma unroll
    for (int off = 256; off > 0; off >>= 1) {
        if (tid < off) red[tid] = fmaxf(red[tid], red[tid + off]);
        __syncthreads();
    }
    float mx = red[0];
    __syncthreads();

    float e = (tid < SEQ) ? expf(sc - mx) : 0.f;
    red[tid] = e;
    __syncthreads();
    #pragma unroll
    for (int off = 256; off > 0; off >>= 1) {
        if (tid < off) red[tid] += red[tid + off];
        __syncthreads();
    }
    float inv = 1.f / red[0];

    float wt = e * inv;
    if (tid < SEQ) {
        w[tid] = wt;
        out[(size_t)BS * DIM + (size_t)b * SEQ + tid] = wt;
    }
    __syncthreads();

    const int sg = tid >> 7;            // 0..3
    const int e4 = tid & 127;           // float4 index
    const float4* fb = (const float4*)(features + (size_t)b * SEQ * DIM);
    float4 acc = make_float4(0.f, 0.f, 0.f, 0.f);
    const int sBeg = sg * 90, sEnd = sBeg + 90;
    #pragma unroll 5
    for (int s = sBeg; s < sEnd; ++s) {
        float ws = w[s];
        float4 v = fb[(size_t)s * 128 + e4];
        acc.x += ws * v.x; acc.y += ws * v.y;
        acc.z += ws * v.z; acc.w += ws * v.w;
    }
    ((float4*)part[sg])[e4] = acc;
    __syncthreads();

    float r = (part[0][tid] + part[1][tid]) + (part[2][tid] + part[3][tid]);
    out[(size_t)b * DIM + tid] = r;
}

// ===================== launch =====================
extern "C" void kernel_launch(void* const* d_in, const int* in_sizes, int n_in,
                              void* d_out, int out_size)
{
    const float* hidden   = (const float*)d_in[0];
    const float* features = (const float*)d_in[1];
    const float* W1_w     = (const float*)d_in[2];
    const float* W1_b     = (const float*)d_in[3];
    const float* W2_w     = (const float*)d_in[4];
    const float* W2_b     = (const float*)d_in[5];
    const float* V_w      = (const float*)d_in[6];
    const float* V_b      = (const float*)d_in[7];
    float* out = (float*)d_out;

    cudaFuncSetAttribute(score_mma_kernel,
                         cudaFuncAttributeMaxDynamicSharedMemorySize, SMEM_BYTES);

    prep_w1_kernel<<<256, 256>>>(W1_w);
    hproj_kernel<<<dim3(16, 8), 256>>>(hidden, W2_w, W2_b);
    score_mma_kernel<<<MTOT / MTILE, 512, SMEM_BYTES>>>(features, W1_b, V_w, V_b);
    softmax_ctx_kernel<<<BS, 512>>>(features, out);
}